// round 1
// baseline (speedup 1.0000x reference)
#include <cuda_runtime.h>
#include <cstdint>

#define BB 4
#define SS 1024
#define DD 1024
#define HH 16
#define DH 64

// -------- scratch (no allocations allowed) --------
__device__ float g_qh[BB * HH * SS * DH];   // [B,H,S,dh]
__device__ float g_kh[BB * HH * SS * DH];
__device__ float g_vh[BB * HH * SS * DH];
__device__ float g_ctx[BB * SS * DD];       // [B,S,H*dh]

// ============================================================
// Kernel 1: per-head QKV projections
//   C[64 rows, 64 cols(head)] = X[4096,1024] @ W_h[1024,64] + b_h
//   grid (4096/64, H, 3), 256 threads, 4x4 micro-tile
// ============================================================
__global__ __launch_bounds__(256) void proj_kernel(
    const float* __restrict__ q, const float* __restrict__ k, const float* __restrict__ v,
    const float* __restrict__ Wq, const float* __restrict__ bq,
    const float* __restrict__ Wk, const float* __restrict__ bk,
    const float* __restrict__ Wv, const float* __restrict__ bv)
{
    const float* X;
    const float* W;
    const float* bias;
    float* out;
    const int z = blockIdx.z;
    if (z == 0)      { X = q; W = Wq; bias = bq; out = g_qh; }
    else if (z == 1) { X = k; W = Wk; bias = bk; out = g_kh; }
    else             { X = v; W = Wv; bias = bv; out = g_vh; }

    const int h  = blockIdx.y;
    const int m0 = blockIdx.x * 64;
    W    += (size_t)h * DD * DH;
    bias += h * DH;

    __shared__ float As[64][16];
    __shared__ float Bs[16][64];

    const int tid = threadIdx.x;
    const int ty  = tid >> 4;    // 0..15
    const int tx  = tid & 15;    // 0..15

    float acc[4][4] = {};

    for (int k0 = 0; k0 < DD; k0 += 16) {
        // A tile 64x16 (row-major, K contiguous)
        {
            int r = tid >> 2;
            int c = (tid & 3) * 4;
            float4 a4 = *(const float4*)(X + (size_t)(m0 + r) * DD + k0 + c);
            *(float4*)&As[r][c] = a4;
        }
        // B tile 16x64
        {
            int r = tid >> 4;
            int c = (tid & 15) * 4;
            float4 b4 = *(const float4*)(W + (size_t)(k0 + r) * DH + c);
            *(float4*)&Bs[r][c] = b4;
        }
        __syncthreads();

        #pragma unroll
        for (int kk = 0; kk < 16; kk++) {
            float a[4], b[4];
            #pragma unroll
            for (int i = 0; i < 4; i++) a[i] = As[ty * 4 + i][kk];
            #pragma unroll
            for (int j = 0; j < 4; j++) b[j] = Bs[kk][tx * 4 + j];
            #pragma unroll
            for (int i = 0; i < 4; i++)
                #pragma unroll
                for (int j = 0; j < 4; j++)
                    acc[i][j] += a[i] * b[j];
        }
        __syncthreads();
    }

    // out layout [B,H,S,dh]
    #pragma unroll
    for (int i = 0; i < 4; i++) {
        int r    = m0 + ty * 4 + i;
        int bidx = r >> 10;
        int s    = r & 1023;
        float* dst = out + (((size_t)bidx * HH + h) * SS + s) * DH + tx * 4;
        #pragma unroll
        for (int j = 0; j < 4; j++)
            dst[j] = acc[i][j] + bias[tx * 4 + j];
    }
}

// ============================================================
// Kernel 2: fused attention per (b*H+h, 32-query tile)
//   - logits into SMEM (32x1024), exact softmax, write score to gmem
//   - ctx[32,64] = score_tile @ vh, write to g_ctx [B,S,D]
//   grid (S/32, B*H), 256 threads, dynamic SMEM 155,648 B
// ============================================================
__global__ __launch_bounds__(256) void attn_kernel(float* __restrict__ score_out)
{
    extern __shared__ float sm[];
    float* qs = sm;                       // 32*64
    float* kt = sm + 32 * 64;             // 64*64 (keys transposed, later V)
    float* sc = sm + 32 * 64 + 64 * 64;   // 32*1024

    const int bh  = blockIdx.y;           // b*H + h
    const int q0  = blockIdx.x * 32;
    const int tid = threadIdx.x;
    const int ty  = tid >> 4;             // 0..15
    const int tx  = tid & 15;             // 0..15

    const float* qh = g_qh + (size_t)bh * SS * DH;
    const float* kh = g_kh + (size_t)bh * SS * DH;
    const float* vh = g_vh + (size_t)bh * SS * DH;

    // load q tile 32x64
    #pragma unroll
    for (int l = 0; l < 2; l++) {
        int lin = tid + l * 256;          // 0..511  (512 float4s)
        int r   = lin >> 4;
        int c   = (lin & 15) * 4;
        *(float4*)&qs[r * 64 + c] = *(const float4*)(qh + (size_t)(q0 + r) * DH + c);
    }

    const int r0 = ty * 2;
    const int r1 = ty * 2 + 1;

    // ---- phase 1: logits ----
    for (int kt0 = 0; kt0 < SS; kt0 += 64) {
        // load K tile transposed: kt[e][key]
        #pragma unroll
        for (int l = 0; l < 4; l++) {
            int lin = tid + l * 256;      // 0..1023
            int key = lin >> 4;
            int c   = (lin & 15) * 4;
            float4 t4 = *(const float4*)(kh + (size_t)(kt0 + key) * DH + c);
            kt[(c + 0) * 64 + key] = t4.x;
            kt[(c + 1) * 64 + key] = t4.y;
            kt[(c + 2) * 64 + key] = t4.z;
            kt[(c + 3) * 64 + key] = t4.w;
        }
        __syncthreads();

        float acc0[4] = {}, acc1[4] = {};
        #pragma unroll 16
        for (int e = 0; e < 64; e++) {
            float a0 = qs[r0 * 64 + e];
            float a1 = qs[r1 * 64 + e];
            #pragma unroll
            for (int j = 0; j < 4; j++) {
                float b = kt[e * 64 + tx * 4 + j];
                acc0[j] += a0 * b;
                acc1[j] += a1 * b;
            }
        }
        #pragma unroll
        for (int j = 0; j < 4; j++) {
            sc[r0 * 1024 + kt0 + tx * 4 + j] = acc0[j] * 0.125f;
            sc[r1 * 1024 + kt0 + tx * 4 + j] = acc1[j] * 0.125f;
        }
        __syncthreads();
    }

    // ---- phase 2: softmax (warp per 4 rows), write score to gmem ----
    {
        const int wid  = tid >> 5;
        const int lane = tid & 31;
        for (int rr = 0; rr < 4; rr++) {
            int r = wid * 4 + rr;
            float* row = sc + r * 1024;
            float mx = row[lane];
            #pragma unroll
            for (int i = 1; i < 32; i++) mx = fmaxf(mx, row[i * 32 + lane]);
            #pragma unroll
            for (int o = 16; o; o >>= 1) mx = fmaxf(mx, __shfl_xor_sync(0xFFFFFFFFu, mx, o));

            float sum = 0.f;
            #pragma unroll
            for (int i = 0; i < 32; i++) {
                float e = __expf(row[i * 32 + lane] - mx);
                row[i * 32 + lane] = e;
                sum += e;
            }
            #pragma unroll
            for (int o = 16; o; o >>= 1) sum += __shfl_xor_sync(0xFFFFFFFFu, sum, o);
            float inv = 1.f / sum;

            float* g = score_out + ((size_t)bh * SS + q0 + r) * SS;
            #pragma unroll
            for (int i = 0; i < 32; i++) {
                float p = row[i * 32 + lane] * inv;
                row[i * 32 + lane] = p;
                g[i * 32 + lane]   = p;
            }
        }
    }
    __syncthreads();

    // ---- phase 3: ctx = score_tile @ vh ----
    float c0[4] = {}, c1[4] = {};
    for (int kt0 = 0; kt0 < SS; kt0 += 64) {
        // load V tile (no transpose): kt[key][e]
        #pragma unroll
        for (int l = 0; l < 4; l++) {
            int lin = tid + l * 256;
            int key = lin >> 4;
            int c   = (lin & 15) * 4;
            *(float4*)&kt[key * 64 + c] =
                *(const float4*)(vh + (size_t)(kt0 + key) * DH + c);
        }
        __syncthreads();

        #pragma unroll 16
        for (int e = 0; e < 64; e++) {
            float a0 = sc[r0 * 1024 + kt0 + e];
            float a1 = sc[r1 * 1024 + kt0 + e];
            #pragma unroll
            for (int j = 0; j < 4; j++) {
                float b = kt[e * 64 + tx * 4 + j];
                c0[j] += a0 * b;
                c1[j] += a1 * b;
            }
        }
        __syncthreads();
    }

    // write ctx in [B,S,H*dh] layout
    {
        const int b = bh >> 4;   // H == 16
        const int h = bh & 15;
        float* d0 = g_ctx + ((size_t)b * SS + q0 + r0) * DD + h * DH + tx * 4;
        float* d1 = g_ctx + ((size_t)b * SS + q0 + r1) * DD + h * DH + tx * 4;
        #pragma unroll
        for (int j = 0; j < 4; j++) { d0[j] = c0[j]; d1[j] = c1[j]; }
    }
}

// ============================================================
// Kernel 3: out = ctx @ Wo + bo   (4096x1024 @ 1024x1024)
//   grid (4096/64, 1024/64), 256 threads, 4x4 micro-tile
// ============================================================
__global__ __launch_bounds__(256) void outproj_kernel(
    const float* __restrict__ Wo, const float* __restrict__ bo,
    float* __restrict__ out)
{
    const int m0 = blockIdx.x * 64;
    const int n0 = blockIdx.y * 64;

    __shared__ float As[64][16];
    __shared__ float Bs[16][64];

    const int tid = threadIdx.x;
    const int ty  = tid >> 4;
    const int tx  = tid & 15;

    float acc[4][4] = {};

    for (int k0 = 0; k0 < DD; k0 += 16) {
        {
            int r = tid >> 2;
            int c = (tid & 3) * 4;
            float4 a4 = *(const float4*)(g_ctx + (size_t)(m0 + r) * DD + k0 + c);
            *(float4*)&As[r][c] = a4;
        }
        {
            int r = tid >> 4;
            int c = (tid & 15) * 4;
            float4 b4 = *(const float4*)(Wo + (size_t)(k0 + r) * DD + n0 + c);
            *(float4*)&Bs[r][c] = b4;
        }
        __syncthreads();

        #pragma unroll
        for (int kk = 0; kk < 16; kk++) {
            float a[4], b[4];
            #pragma unroll
            for (int i = 0; i < 4; i++) a[i] = As[ty * 4 + i][kk];
            #pragma unroll
            for (int j = 0; j < 4; j++) b[j] = Bs[kk][tx * 4 + j];
            #pragma unroll
            for (int i = 0; i < 4; i++)
                #pragma unroll
                for (int j = 0; j < 4; j++)
                    acc[i][j] += a[i] * b[j];
        }
        __syncthreads();
    }

    #pragma unroll
    for (int i = 0; i < 4; i++) {
        int r = m0 + ty * 4 + i;
        float* dst = out + (size_t)r * DD + n0 + tx * 4;
        #pragma unroll
        for (int j = 0; j < 4; j++)
            dst[j] = acc[i][j] + bo[n0 + tx * 4 + j];
    }
}

// ============================================================
extern "C" void kernel_launch(void* const* d_in, const int* in_sizes, int n_in,
                              void* d_out, int out_size)
{
    const float* q  = (const float*)d_in[0];
    const float* k  = (const float*)d_in[1];
    const float* v  = (const float*)d_in[2];
    const float* Wq = (const float*)d_in[3];
    const float* bq = (const float*)d_in[4];
    const float* Wk = (const float*)d_in[5];
    const float* bk = (const float*)d_in[6];
    const float* Wv = (const float*)d_in[7];
    const float* bv = (const float*)d_in[8];
    const float* Wo = (const float*)d_in[9];
    const float* bo = (const float*)d_in[10];

    float* out   = (float*)d_out;
    float* score = out + (size_t)BB * SS * DD;   // out first, then score

    const int attn_smem = (32 * 64 + 64 * 64 + 32 * 1024) * (int)sizeof(float); // 155,648 B
    cudaFuncSetAttribute(attn_kernel,
                         cudaFuncAttributeMaxDynamicSharedMemorySize, attn_smem);

    // 1) QKV projections
    {
        dim3 grid(BB * SS / 64, HH, 3);
        proj_kernel<<<grid, 256>>>(q, k, v, Wq, bq, Wk, bk, Wv, bv);
    }
    // 2) fused attention (softmax + score write + ctx)
    {
        dim3 grid(SS / 32, BB * HH);
        attn_kernel<<<grid, 256, attn_smem>>>(score);
    }
    // 3) output projection
    {
        dim3 grid(BB * SS / 64, DD / 64);
        outproj_kernel<<<grid, 256>>>(Wo, bo, out);
    }
}

// round 2
// speedup vs baseline: 1.2053x; 1.2053x over previous
#include <cuda_runtime.h>
#include <cstdint>

#define BB 4
#define SS 1024
#define DD 1024
#define HH 16
#define DH 64

// -------- scratch (no allocations allowed) --------
__device__ float g_qh[BB * HH * SS * DH];   // [B,H,S,dh]
__device__ float g_kh[BB * HH * SS * DH];
__device__ float g_vh[BB * HH * SS * DH];
__device__ float g_ctx[BB * SS * DD];       // [B,S,H*dh]

// ============================================================
// Kernel 1: QKV projections as 3x GEMM  C[4096,1024] = X @ Wz
//   Wz logical [1024,1024] with col n -> (h = n>>6, e = n&63)
//   128x128 block tile, K-step 16, 256 threads, 8x8 micro-tile
// ============================================================
__global__ __launch_bounds__(256) void proj_kernel(
    const float* __restrict__ q, const float* __restrict__ k, const float* __restrict__ v,
    const float* __restrict__ Wq, const float* __restrict__ bq,
    const float* __restrict__ Wk, const float* __restrict__ bk,
    const float* __restrict__ Wv, const float* __restrict__ bv)
{
    const float *X, *W, *bias;
    float* out;
    const int z = blockIdx.z;
    if (z == 0)      { X = q; W = Wq; bias = bq; out = g_qh; }
    else if (z == 1) { X = k; W = Wk; bias = bk; out = g_kh; }
    else             { X = v; W = Wv; bias = bv; out = g_vh; }

    const int m0 = blockIdx.x * 128;
    const int n0 = blockIdx.y * 128;

    __shared__ float As[16][132];   // transposed: As[k][m], padded
    __shared__ float Bs[16][128];   // Bs[k][n]

    const int tid = threadIdx.x;
    const int tx  = tid & 15;           // col group
    const int ty  = tid >> 4;           // row group
    const int rowbase = ty * 8;
    const int colbase = tx * 8;

    // loader indices
    const int a_r  = tid >> 2;          // 0..63 (rows a_r, a_r+64)
    const int a_kg = (tid & 3) * 4;     // k offset 0,4,8,12
    const int b_k  = tid >> 5;          // 0..7 (k rows b_k, b_k+8)
    const int b_nc = (tid & 31) * 4;    // col offset 0..124

    float acc[8][8] = {};

    for (int k0 = 0; k0 < DD; k0 += 16) {
        // A tile 128x16 -> transposed store (coalesced 64B-per-row reads)
        #pragma unroll
        for (int i = 0; i < 2; i++) {
            int r = a_r + i * 64;
            float4 a4 = *(const float4*)(X + (size_t)(m0 + r) * DD + k0 + a_kg);
            As[a_kg + 0][r] = a4.x;
            As[a_kg + 1][r] = a4.y;
            As[a_kg + 2][r] = a4.z;
            As[a_kg + 3][r] = a4.w;
        }
        // B tile 16x128: B[k][n] = W[h][k][e]
        #pragma unroll
        for (int i = 0; i < 2; i++) {
            int kk = b_k + i * 8;
            int n  = n0 + b_nc;
            int h  = n >> 6;
            int e  = n & 63;
            *(float4*)&Bs[kk][b_nc] =
                *(const float4*)(W + ((size_t)h * DD + (k0 + kk)) * DH + e);
        }
        __syncthreads();

        #pragma unroll
        for (int kk = 0; kk < 16; kk++) {
            float a[8], b[8];
            *(float4*)&a[0] = *(const float4*)&As[kk][rowbase];
            *(float4*)&a[4] = *(const float4*)&As[kk][rowbase + 4];
            *(float4*)&b[0] = *(const float4*)&Bs[kk][colbase];
            *(float4*)&b[4] = *(const float4*)&Bs[kk][colbase + 4];
            #pragma unroll
            for (int i = 0; i < 8; i++)
                #pragma unroll
                for (int j = 0; j < 8; j++)
                    acc[i][j] += a[i] * b[j];
        }
        __syncthreads();
    }

    // epilogue: bias + write to [B,H,S,dh]
    const int n  = n0 + colbase;
    const int h  = n >> 6;
    const int e  = n & 63;
    float bv8[8];
    *(float4*)&bv8[0] = *(const float4*)(bias + h * DH + e);
    *(float4*)&bv8[4] = *(const float4*)(bias + h * DH + e + 4);

    #pragma unroll
    for (int i = 0; i < 8; i++) {
        int m    = m0 + rowbase + i;
        int bidx = m >> 10;
        int s    = m & 1023;
        float* dst = out + (((size_t)bidx * HH + h) * SS + s) * DH + e;
        float4 o0, o1;
        o0.x = acc[i][0] + bv8[0]; o0.y = acc[i][1] + bv8[1];
        o0.z = acc[i][2] + bv8[2]; o0.w = acc[i][3] + bv8[3];
        o1.x = acc[i][4] + bv8[4]; o1.y = acc[i][5] + bv8[5];
        o1.z = acc[i][6] + bv8[6]; o1.w = acc[i][7] + bv8[7];
        *(float4*)dst       = o0;
        *(float4*)(dst + 4) = o1;
    }
}

// ============================================================
// Kernel 2: fused attention per (b*H+h, 32-query tile)
//   phase1: logits 32x1024 into smem, 256-key chunks, 4x8 microtile
//   phase2: exact softmax + score write (streaming stores)
//   phase3: ctx = score @ V, key-split 4-way, 4qx8e microtile
//   256 threads, dynamic smem 207,360 B
// ============================================================
#define QS_STR 36
#define KT_STR 260
#define SC_STR 1028

__global__ __launch_bounds__(256) void attn_kernel(float* __restrict__ score_out)
{
    extern __shared__ float sm[];
    float* qs = sm;                           // [64][36]   q transposed (e-major)
    float* kt = sm + 64 * QS_STR;             // [64][260]  K^T chunk / V chunk / reduce
    float* sc = sm + 64 * QS_STR + 64 * KT_STR; // [32][1028] logits/scores

    const int bh  = blockIdx.y;
    const int q0  = blockIdx.x * 32;
    const int tid = threadIdx.x;

    const float* qh = g_qh + (size_t)bh * SS * DH;
    const float* kh = g_kh + (size_t)bh * SS * DH;
    const float* vh = g_vh + (size_t)bh * SS * DH;

    // ---- load q tile transposed: qs[e][q] ----
    #pragma unroll
    for (int i = 0; i < 2; i++) {
        int lin  = tid + i * 256;
        int qrow = lin & 31;
        int c    = (lin >> 5) * 4;
        float4 t = *(const float4*)(qh + (size_t)(q0 + qrow) * DH + c);
        qs[(c + 0) * QS_STR + qrow] = t.x;
        qs[(c + 1) * QS_STR + qrow] = t.y;
        qs[(c + 2) * QS_STR + qrow] = t.z;
        qs[(c + 3) * QS_STR + qrow] = t.w;
    }
    __syncthreads();

    // ---- phase 1: logits ----
    {
        const int ty = tid >> 5;   // q group (warp id), rows ty*4..+3
        const int tx = tid & 31;   // key group, keys tx*8..+7
        for (int c0 = 0; c0 < SS; c0 += 256) {
            // load K chunk transposed: kt[e][key] (key-major lanes: conflict-free STS)
            #pragma unroll
            for (int i = 0; i < 16; i++) {
                int lin = tid + i * 256;     // float4 index 0..4095
                int key = lin & 255;
                int c   = (lin >> 8) * 4;
                float4 t = *(const float4*)(kh + (size_t)(c0 + key) * DH + c);
                kt[(c + 0) * KT_STR + key] = t.x;
                kt[(c + 1) * KT_STR + key] = t.y;
                kt[(c + 2) * KT_STR + key] = t.z;
                kt[(c + 3) * KT_STR + key] = t.w;
            }
            __syncthreads();

            float acc[4][8] = {};
            #pragma unroll 8
            for (int kk = 0; kk < 64; kk++) {
                float a[4], b[8];
                *(float4*)&a[0] = *(const float4*)&qs[kk * QS_STR + ty * 4];
                *(float4*)&b[0] = *(const float4*)&kt[kk * KT_STR + tx * 8];
                *(float4*)&b[4] = *(const float4*)&kt[kk * KT_STR + tx * 8 + 4];
                #pragma unroll
                for (int i = 0; i < 4; i++)
                    #pragma unroll
                    for (int j = 0; j < 8; j++)
                        acc[i][j] += a[i] * b[j];
            }
            #pragma unroll
            for (int i = 0; i < 4; i++) {
                float4 s0, s1;
                s0.x = acc[i][0] * 0.125f; s0.y = acc[i][1] * 0.125f;
                s0.z = acc[i][2] * 0.125f; s0.w = acc[i][3] * 0.125f;
                s1.x = acc[i][4] * 0.125f; s1.y = acc[i][5] * 0.125f;
                s1.z = acc[i][6] * 0.125f; s1.w = acc[i][7] * 0.125f;
                *(float4*)&sc[(ty * 4 + i) * SC_STR + c0 + tx * 8]     = s0;
                *(float4*)&sc[(ty * 4 + i) * SC_STR + c0 + tx * 8 + 4] = s1;
            }
            __syncthreads();
        }
    }

    // ---- phase 2: softmax (warp per 4 rows) + streaming score write ----
    {
        const int wid  = tid >> 5;
        const int lane = tid & 31;
        for (int rr = 0; rr < 4; rr++) {
            int r = wid * 4 + rr;
            float* row = sc + r * SC_STR;
            float mx = row[lane];
            #pragma unroll
            for (int i = 1; i < 32; i++) mx = fmaxf(mx, row[i * 32 + lane]);
            #pragma unroll
            for (int o = 16; o; o >>= 1) mx = fmaxf(mx, __shfl_xor_sync(0xFFFFFFFFu, mx, o));

            float sum = 0.f;
            #pragma unroll
            for (int i = 0; i < 32; i++) {
                float e = __expf(row[i * 32 + lane] - mx);
                row[i * 32 + lane] = e;
                sum += e;
            }
            #pragma unroll
            for (int o = 16; o; o >>= 1) sum += __shfl_xor_sync(0xFFFFFFFFu, sum, o);
            float inv = 1.f / sum;

            float* g = score_out + ((size_t)bh * SS + q0 + r) * SS;
            #pragma unroll
            for (int i = 0; i < 32; i++) {
                float p = row[i * 32 + lane] * inv;
                row[i * 32 + lane] = p;
                __stcs(&g[i * 32 + lane], p);
            }
        }
    }
    __syncthreads();

    // ---- phase 3: ctx = score @ V, key-split 4-way ----
    {
        const int kq  = tid >> 6;    // key quarter 0..3
        const int pos = tid & 63;
        const int qg  = pos >> 3;    // q rows qg*4..+3
        const int eg  = pos & 7;     // e cols eg*8..+7
        float* vs = kt;              // reuse: vs[key][e], 256x64

        float cacc[4][8] = {};
        for (int c0 = 0; c0 < SS; c0 += 256) {
            // load V chunk (no transpose, fully coalesced)
            #pragma unroll
            for (int i = 0; i < 16; i++) {
                int lin = tid + i * 256;
                int key = lin >> 4;
                int c   = (lin & 15) * 4;
                *(float4*)&vs[key * 64 + c] =
                    *(const float4*)(vh + (size_t)(c0 + key) * DH + c);
            }
            __syncthreads();

            #pragma unroll 4
            for (int kk = 0; kk < 64; kk++) {
                int key = kq * 64 + kk;
                float a[4], b[8];
                #pragma unroll
                for (int i = 0; i < 4; i++)
                    a[i] = sc[(qg * 4 + i) * SC_STR + c0 + key];
                *(float4*)&b[0] = *(const float4*)&vs[key * 64 + eg * 8];
                *(float4*)&b[4] = *(const float4*)&vs[key * 64 + eg * 8 + 4];
                #pragma unroll
                for (int i = 0; i < 4; i++)
                    #pragma unroll
                    for (int j = 0; j < 8; j++)
                        cacc[i][j] += a[i] * b[j];
            }
            __syncthreads();
        }

        // reduce 4 partials via smem (kt reused; stride 33 avoids conflicts)
        float* red = kt;
        #pragma unroll
        for (int i = 0; i < 4; i++)
            #pragma unroll
            for (int j = 0; j < 8; j++)
                red[(kq * 64 + pos) * 33 + i * 8 + j] = cacc[i][j];
        __syncthreads();

        if (tid < 64) {
            const int pqg = tid >> 3;
            const int peg = tid & 7;
            const int b   = bh >> 4;
            const int h   = bh & 15;
            #pragma unroll
            for (int i = 0; i < 4; i++) {
                float o[8];
                #pragma unroll
                for (int j = 0; j < 8; j++) {
                    o[j] = red[(0 * 64 + tid) * 33 + i * 8 + j]
                         + red[(1 * 64 + tid) * 33 + i * 8 + j]
                         + red[(2 * 64 + tid) * 33 + i * 8 + j]
                         + red[(3 * 64 + tid) * 33 + i * 8 + j];
                }
                float* dst = g_ctx + ((size_t)b * SS + q0 + pqg * 4 + i) * DD
                           + h * DH + peg * 8;
                *(float4*)dst       = *(float4*)&o[0];
                *(float4*)(dst + 4) = *(float4*)&o[4];
            }
        }
    }
}

// ============================================================
// Kernel 3: out = ctx @ Wo + bo  (4096x1024x1024)
//   same 128x128x16 SGEMM skeleton
// ============================================================
__global__ __launch_bounds__(256) void outproj_kernel(
    const float* __restrict__ Wo, const float* __restrict__ bo,
    float* __restrict__ out)
{
    const int m0 = blockIdx.x * 128;
    const int n0 = blockIdx.y * 128;

    __shared__ float As[16][132];
    __shared__ float Bs[16][128];

    const int tid = threadIdx.x;
    const int tx  = tid & 15;
    const int ty  = tid >> 4;
    const int rowbase = ty * 8;
    const int colbase = tx * 8;

    const int a_r  = tid >> 2;
    const int a_kg = (tid & 3) * 4;
    const int b_k  = tid >> 5;
    const int b_nc = (tid & 31) * 4;

    float acc[8][8] = {};

    for (int k0 = 0; k0 < DD; k0 += 16) {
        #pragma unroll
        for (int i = 0; i < 2; i++) {
            int r = a_r + i * 64;
            float4 a4 = *(const float4*)(g_ctx + (size_t)(m0 + r) * DD + k0 + a_kg);
            As[a_kg + 0][r] = a4.x;
            As[a_kg + 1][r] = a4.y;
            As[a_kg + 2][r] = a4.z;
            As[a_kg + 3][r] = a4.w;
        }
        #pragma unroll
        for (int i = 0; i < 2; i++) {
            int kk = b_k + i * 8;
            *(float4*)&Bs[kk][b_nc] =
                *(const float4*)(Wo + (size_t)(k0 + kk) * DD + n0 + b_nc);
        }
        __syncthreads();

        #pragma unroll
        for (int kk = 0; kk < 16; kk++) {
            float a[8], b[8];
            *(float4*)&a[0] = *(const float4*)&As[kk][rowbase];
            *(float4*)&a[4] = *(const float4*)&As[kk][rowbase + 4];
            *(float4*)&b[0] = *(const float4*)&Bs[kk][colbase];
            *(float4*)&b[4] = *(const float4*)&Bs[kk][colbase + 4];
            #pragma unroll
            for (int i = 0; i < 8; i++)
                #pragma unroll
                for (int j = 0; j < 8; j++)
                    acc[i][j] += a[i] * b[j];
        }
        __syncthreads();
    }

    float bv8[8];
    *(float4*)&bv8[0] = *(const float4*)(bo + n0 + colbase);
    *(float4*)&bv8[4] = *(const float4*)(bo + n0 + colbase + 4);

    #pragma unroll
    for (int i = 0; i < 8; i++) {
        int m = m0 + rowbase + i;
        float* dst = out + (size_t)m * DD + n0 + colbase;
        float4 o0, o1;
        o0.x = acc[i][0] + bv8[0]; o0.y = acc[i][1] + bv8[1];
        o0.z = acc[i][2] + bv8[2]; o0.w = acc[i][3] + bv8[3];
        o1.x = acc[i][4] + bv8[4]; o1.y = acc[i][5] + bv8[5];
        o1.z = acc[i][6] + bv8[6]; o1.w = acc[i][7] + bv8[7];
        *(float4*)dst       = o0;
        *(float4*)(dst + 4) = o1;
    }
}

// ============================================================
extern "C" void kernel_launch(void* const* d_in, const int* in_sizes, int n_in,
                              void* d_out, int out_size)
{
    const float* q  = (const float*)d_in[0];
    const float* k  = (const float*)d_in[1];
    const float* v  = (const float*)d_in[2];
    const float* Wq = (const float*)d_in[3];
    const float* bq = (const float*)d_in[4];
    const float* Wk = (const float*)d_in[5];
    const float* bk = (const float*)d_in[6];
    const float* Wv = (const float*)d_in[7];
    const float* bv = (const float*)d_in[8];
    const float* Wo = (const float*)d_in[9];
    const float* bo = (const float*)d_in[10];

    float* out   = (float*)d_out;
    float* score = out + (size_t)BB * SS * DD;

    const int attn_smem = (64 * QS_STR + 64 * KT_STR + 32 * SC_STR) * (int)sizeof(float); // 207,360
    cudaFuncSetAttribute(attn_kernel,
                         cudaFuncAttributeMaxDynamicSharedMemorySize, attn_smem);

    {
        dim3 grid(BB * SS / 128, DD / 128, 3);
        proj_kernel<<<grid, 256>>>(q, k, v, Wq, bq, Wk, bk, Wv, bv);
    }
    {
        dim3 grid(SS / 32, BB * HH);
        attn_kernel<<<grid, 256, attn_smem>>>(score);
    }
    {
        dim3 grid(BB * SS / 128, DD / 128);
        outproj_kernel<<<grid, 256>>>(Wo, bo, out);
    }
}

// round 4
// speedup vs baseline: 1.6233x; 1.3468x over previous
#include <cuda_runtime.h>
#include <cuda_bf16.h>
#include <cstdint>

#define BB 4
#define SS 1024
#define DD 1024
#define HH 16
#define DH 64
#define MTOT (BB * SS)          // 4096

// ================= scratch (static device memory; no allocs) =================
__device__ float g_qh[BB * HH * SS * DH];   // [B,H,S,dh] fp32 (attn inputs)
__device__ float g_kh[BB * HH * SS * DH];
__device__ float g_vh[BB * HH * SS * DH];

__device__ __nv_bfloat16 g_q_hi[MTOT * DD], g_q_lo[MTOT * DD];
__device__ __nv_bfloat16 g_k_hi[MTOT * DD], g_k_lo[MTOT * DD];
__device__ __nv_bfloat16 g_v_hi[MTOT * DD], g_v_lo[MTOT * DD];
__device__ __nv_bfloat16 g_wq_hi[DD * DD], g_wq_lo[DD * DD];   // W^T [n][k]
__device__ __nv_bfloat16 g_wk_hi[DD * DD], g_wk_lo[DD * DD];
__device__ __nv_bfloat16 g_wv_hi[DD * DD], g_wv_lo[DD * DD];
__device__ __nv_bfloat16 g_wo_hi[DD * DD], g_wo_lo[DD * DD];
__device__ __nv_bfloat16 g_cx_hi[MTOT * DD], g_cx_lo[MTOT * DD]; // ctx bf16

// ================= helpers =================
static __device__ __forceinline__ uint32_t smem_u32(const void* p) {
    uint32_t a;
    asm("{ .reg .u64 t; cvta.to.shared.u64 t, %1; cvt.u32.u64 %0, t; }"
        : "=r"(a) : "l"(p));
    return a;
}

#define CP_ASYNC16(dst, src) \
    asm volatile("cp.async.cg.shared.global [%0], [%1], 16;" \
                 :: "r"(dst), "l"(src) : "memory")
#define CP_COMMIT()  asm volatile("cp.async.commit_group;" ::: "memory")
#define CP_WAIT(n)   asm volatile("cp.async.wait_group %0;" :: "n"(n) : "memory")

#define LDSM_X4(r, a) \
    asm volatile("ldmatrix.sync.aligned.m8n8.x4.shared.b16 {%0,%1,%2,%3}, [%4];" \
                 : "=r"((r)[0]), "=r"((r)[1]), "=r"((r)[2]), "=r"((r)[3]) : "r"(a))
#define LDSM_X2(r, a) \
    asm volatile("ldmatrix.sync.aligned.m8n8.x2.shared.b16 {%0,%1}, [%2];" \
                 : "=r"((r)[0]), "=r"((r)[1]) : "r"(a))
#define MMA16816(c, a, b) \
    asm volatile("mma.sync.aligned.m16n8k16.row.col.f32.bf16.bf16.f32 " \
                 "{%0,%1,%2,%3}, {%4,%5,%6,%7}, {%8,%9}, {%0,%1,%2,%3};" \
                 : "+f"((c)[0]), "+f"((c)[1]), "+f"((c)[2]), "+f"((c)[3]) \
                 : "r"((a)[0]), "r"((a)[1]), "r"((a)[2]), "r"((a)[3]), \
                   "r"((b)[0]), "r"((b)[1]))

// ================= conversion kernels =================
__global__ __launch_bounds__(256) void cvt_split_kernel(
    const float* __restrict__ src, __nv_bfloat16* __restrict__ hi,
    __nv_bfloat16* __restrict__ lo)
{
    int i = (blockIdx.x * 256 + threadIdx.x) * 4;
    float4 f = *(const float4*)(src + i);
    __nv_bfloat16 h[4], l[4];
    float v[4] = {f.x, f.y, f.z, f.w};
    #pragma unroll
    for (int j = 0; j < 4; j++) {
        h[j] = __float2bfloat16(v[j]);
        l[j] = __float2bfloat16(v[j] - __bfloat162float(h[j]));
    }
    *(uint2*)(hi + i) = *(uint2*)h;
    *(uint2*)(lo + i) = *(uint2*)l;
}

// weight transpose + split: logical W[k][n] -> Wt[n][k] bf16 hi/lo
// interleaved=1: W (k,n) at W[(n>>6)*65536 + k*64 + (n&63)]  ([H,D,dh])
// interleaved=0: W (k,n) at W[k*1024 + n]                    (Wo)
__global__ __launch_bounds__(256) void cvt_wt_kernel(
    const float* __restrict__ W, __nv_bfloat16* __restrict__ hi,
    __nv_bfloat16* __restrict__ lo, int interleaved)
{
    __shared__ float t[32][33];
    const int tx = threadIdx.x, ty = threadIdx.y;
    const int k0 = blockIdx.x * 32, n0 = blockIdx.y * 32;

    #pragma unroll
    for (int i = 0; i < 4; i++) {
        int k = k0 + ty + i * 8;
        int n = n0 + tx;
        size_t a = interleaved ? ((size_t)(n >> 6) * 65536 + (size_t)k * 64 + (n & 63))
                               : ((size_t)k * 1024 + n);
        t[ty + i * 8][tx] = W[a];
    }
    __syncthreads();
    #pragma unroll
    for (int i = 0; i < 4; i++) {
        int n = n0 + ty + i * 8;
        int k = k0 + tx;
        float v = t[tx][ty + i * 8];
        __nv_bfloat16 h = __float2bfloat16(v);
        hi[(size_t)n * 1024 + k] = h;
        lo[(size_t)n * 1024 + k] = __float2bfloat16(v - __bfloat162float(h));
    }
}

// ================= mma.sync bf16-split GEMM =================
//   C[4096,1024] = A[4096,1024] @ Bt[n][k]^T + bias[n]
//   128x128 CTA tile, K-chunk 64, 2-stage cp.async, 8 warps (2m x 4n)
//   mode 0: C layout [B,H,S,dh]   mode 1: C row-major [m][n]
#define KSTRIDE 72                       // padded bf16 row stride (144 B)
#define TILE_B  (128 * KSTRIDE * 2)      // 18432 B per tile
#define OFF_AH  0
#define OFF_AL  (TILE_B)
#define OFF_BH  (2 * TILE_B)
#define OFF_BL  (3 * TILE_B)
#define STAGE_B (4 * TILE_B)             // 73728 B

__global__ __launch_bounds__(256) void gemm_bf16_kernel(
    const __nv_bfloat16* __restrict__ Ahi, const __nv_bfloat16* __restrict__ Alo,
    const __nv_bfloat16* __restrict__ Bhi, const __nv_bfloat16* __restrict__ Blo,
    const float* __restrict__ bias, float* __restrict__ C, int mode)
{
    extern __shared__ char sm[];
    const uint32_t smb = smem_u32(sm);

    const int tid    = threadIdx.x;
    const int lane   = tid & 31;
    const int warp   = tid >> 5;
    const int warp_m = warp >> 2;        // 0..1
    const int warp_n = warp & 3;         // 0..3
    const int m0 = blockIdx.x * 128;
    const int n0 = blockIdx.y * 128;

    // ldmatrix per-lane base offsets (bytes)
    const uint32_t aoff = ((warp_m * 64 + (lane & 15)) * KSTRIDE + ((lane >> 4) * 8)) * 2;
    const uint32_t boff = ((warp_n * 32 + (lane & 7)) * KSTRIDE + (((lane >> 3) & 1) * 8)) * 2;

    // loader indices
    const int l_row = tid >> 1;              // used below via lin
    (void)l_row;

    float acc[4][4][4] = {};

    // ---- stage issue ----
    auto issue = [&](int c) {
        const uint32_t sb = smb + (c & 1) * STAGE_B;
        const int k0 = c * 64;
        #pragma unroll
        for (int i = 0; i < 4; i++) {
            int lin = tid + i * 256;         // 0..1023
            int row = lin >> 3;              // 0..127
            int cg  = lin & 7;               // 16B group
            uint32_t so = (uint32_t)(row * KSTRIDE * 2 + cg * 16);
            size_t ga = (size_t)(m0 + row) * DD + k0 + cg * 8;
            size_t gb = (size_t)(n0 + row) * DD + k0 + cg * 8;
            CP_ASYNC16(sb + OFF_AH + so, Ahi + ga);
            CP_ASYNC16(sb + OFF_AL + so, Alo + ga);
            CP_ASYNC16(sb + OFF_BH + so, Bhi + gb);
            CP_ASYNC16(sb + OFF_BL + so, Blo + gb);
        }
    };

    issue(0);
    CP_COMMIT();

    for (int c = 0; c < DD / 64; c++) {
        if (c + 1 < DD / 64) {
            issue(c + 1);
            CP_COMMIT();
            CP_WAIT(1);
        } else {
            CP_WAIT(0);
        }
        __syncthreads();

        const uint32_t sb = smb + (c & 1) * STAGE_B;
        #pragma unroll
        for (int kk = 0; kk < 4; kk++) {
            const uint32_t kby = kk * 32;    // 16 bf16 = 32 B
            uint32_t ah[4][4], al[4][4];
            #pragma unroll
            for (int mf = 0; mf < 4; mf++) {
                uint32_t ra = sb + aoff + (uint32_t)(mf * 16 * KSTRIDE * 2) + kby;
                LDSM_X4(ah[mf], ra + OFF_AH);
                LDSM_X4(al[mf], ra + OFF_AL);
            }
            uint32_t bh[4][2], bl[4][2];
            #pragma unroll
            for (int nf = 0; nf < 4; nf++) {
                uint32_t rb = sb + boff + (uint32_t)(nf * 8 * KSTRIDE * 2) + kby;
                LDSM_X2(bh[nf], rb + OFF_BH);
                LDSM_X2(bl[nf], rb + OFF_BL);
            }
            #pragma unroll
            for (int mf = 0; mf < 4; mf++)
                #pragma unroll
                for (int nf = 0; nf < 4; nf++) {
                    MMA16816(acc[mf][nf], ah[mf], bh[nf]);
                    MMA16816(acc[mf][nf], ah[mf], bl[nf]);
                    MMA16816(acc[mf][nf], al[mf], bh[nf]);
                }
        }
        __syncthreads();
    }

    // ---- epilogue ----
    const int lr = lane >> 2;
    const int lc = (lane & 3) * 2;
    #pragma unroll
    for (int mf = 0; mf < 4; mf++) {
        #pragma unroll
        for (int nf = 0; nf < 4; nf++) {
            int n = n0 + warp_n * 32 + nf * 8 + lc;
            float bv0 = bias[n], bv1 = bias[n + 1];
            #pragma unroll
            for (int half = 0; half < 2; half++) {
                int m = m0 + warp_m * 64 + mf * 16 + lr + half * 8;
                float2 val;
                val.x = acc[mf][nf][half * 2 + 0] + bv0;
                val.y = acc[mf][nf][half * 2 + 1] + bv1;
                float* dst;
                if (mode == 0) {
                    int bidx = m >> 10, s = m & 1023;
                    int h = n >> 6, e = n & 63;
                    dst = C + (((size_t)bidx * HH + h) * SS + s) * DH + e;
                } else {
                    dst = C + (size_t)m * DD + n;
                }
                *(float2*)dst = val;
            }
        }
    }
}

// ================= fused attention (R2-validated core, bf16 ctx epilogue) ====
#define QS_STR 36
#define KT_STR 260
#define SC_STR 1028

__global__ __launch_bounds__(256) void attn_kernel(float* __restrict__ score_out)
{
    extern __shared__ float smf[];
    float* qs = smf;
    float* kt = smf + 64 * QS_STR;
    float* sc = smf + 64 * QS_STR + 64 * KT_STR;

    const int bh  = blockIdx.y;
    const int q0  = blockIdx.x * 32;
    const int tid = threadIdx.x;

    const float* qh = g_qh + (size_t)bh * SS * DH;
    const float* kh = g_kh + (size_t)bh * SS * DH;
    const float* vh = g_vh + (size_t)bh * SS * DH;

    #pragma unroll
    for (int i = 0; i < 2; i++) {
        int lin  = tid + i * 256;
        int qrow = lin & 31;
        int c    = (lin >> 5) * 4;
        float4 t = *(const float4*)(qh + (size_t)(q0 + qrow) * DH + c);
        qs[(c + 0) * QS_STR + qrow] = t.x;
        qs[(c + 1) * QS_STR + qrow] = t.y;
        qs[(c + 2) * QS_STR + qrow] = t.z;
        qs[(c + 3) * QS_STR + qrow] = t.w;
    }
    __syncthreads();

    // phase 1: logits
    {
        const int ty = tid >> 5;
        const int tx = tid & 31;
        for (int c0 = 0; c0 < SS; c0 += 256) {
            #pragma unroll
            for (int i = 0; i < 16; i++) {
                int lin = tid + i * 256;
                int key = lin & 255;
                int c   = (lin >> 8) * 4;
                float4 t = *(const float4*)(kh + (size_t)(c0 + key) * DH + c);
                kt[(c + 0) * KT_STR + key] = t.x;
                kt[(c + 1) * KT_STR + key] = t.y;
                kt[(c + 2) * KT_STR + key] = t.z;
                kt[(c + 3) * KT_STR + key] = t.w;
            }
            __syncthreads();

            float acc[4][8] = {};
            #pragma unroll 8
            for (int kk = 0; kk < 64; kk++) {
                float a[4], b[8];
                *(float4*)&a[0] = *(const float4*)&qs[kk * QS_STR + ty * 4];
                *(float4*)&b[0] = *(const float4*)&kt[kk * KT_STR + tx * 8];
                *(float4*)&b[4] = *(const float4*)&kt[kk * KT_STR + tx * 8 + 4];
                #pragma unroll
                for (int i = 0; i < 4; i++)
                    #pragma unroll
                    for (int j = 0; j < 8; j++)
                        acc[i][j] += a[i] * b[j];
            }
            #pragma unroll
            for (int i = 0; i < 4; i++) {
                float4 s0, s1;
                s0.x = acc[i][0] * 0.125f; s0.y = acc[i][1] * 0.125f;
                s0.z = acc[i][2] * 0.125f; s0.w = acc[i][3] * 0.125f;
                s1.x = acc[i][4] * 0.125f; s1.y = acc[i][5] * 0.125f;
                s1.z = acc[i][6] * 0.125f; s1.w = acc[i][7] * 0.125f;
                *(float4*)&sc[(ty * 4 + i) * SC_STR + c0 + tx * 8]     = s0;
                *(float4*)&sc[(ty * 4 + i) * SC_STR + c0 + tx * 8 + 4] = s1;
            }
            __syncthreads();
        }
    }

    // phase 2: softmax + score write
    {
        const int wid  = tid >> 5;
        const int lane = tid & 31;
        for (int rr = 0; rr < 4; rr++) {
            int r = wid * 4 + rr;
            float* row = sc + r * SC_STR;
            float mx = row[lane];
            #pragma unroll
            for (int i = 1; i < 32; i++) mx = fmaxf(mx, row[i * 32 + lane]);
            #pragma unroll
            for (int o = 16; o; o >>= 1) mx = fmaxf(mx, __shfl_xor_sync(0xFFFFFFFFu, mx, o));

            float sum = 0.f;
            #pragma unroll
            for (int i = 0; i < 32; i++) {
                float e = __expf(row[i * 32 + lane] - mx);
                row[i * 32 + lane] = e;
                sum += e;
            }
            #pragma unroll
            for (int o = 16; o; o >>= 1) sum += __shfl_xor_sync(0xFFFFFFFFu, sum, o);
            float inv = 1.f / sum;

            float* g = score_out + ((size_t)bh * SS + q0 + r) * SS;
            #pragma unroll
            for (int i = 0; i < 32; i++) {
                float p = row[i * 32 + lane] * inv;
                row[i * 32 + lane] = p;
                __stcs(&g[i * 32 + lane], p);
            }
        }
    }
    __syncthreads();

    // phase 3: ctx = score @ V (key-split 4-way) -> bf16 hi/lo
    {
        const int kq  = tid >> 6;
        const int pos = tid & 63;
        const int qg  = pos >> 3;
        const int eg  = pos & 7;
        float* vs = kt;

        float cacc[4][8] = {};
        for (int c0 = 0; c0 < SS; c0 += 256) {
            #pragma unroll
            for (int i = 0; i < 16; i++) {
                int lin = tid + i * 256;
                int key = lin >> 4;
                int c   = (lin & 15) * 4;
                *(float4*)&vs[key * 64 + c] =
                    *(const float4*)(vh + (size_t)(c0 + key) * DH + c);
            }
            __syncthreads();

            #pragma unroll 4
            for (int kk = 0; kk < 64; kk++) {
                int key = kq * 64 + kk;
                float a[4], b[8];
                #pragma unroll
                for (int i = 0; i < 4; i++)
                    a[i] = sc[(qg * 4 + i) * SC_STR + c0 + key];
                *(float4*)&b[0] = *(const float4*)&vs[key * 64 + eg * 8];
                *(float4*)&b[4] = *(const float4*)&vs[key * 64 + eg * 8 + 4];
                #pragma unroll
                for (int i = 0; i < 4; i++)
                    #pragma unroll
                    for (int j = 0; j < 8; j++)
                        cacc[i][j] += a[i] * b[j];
            }
            __syncthreads();
        }

        float* red = kt;
        #pragma unroll
        for (int i = 0; i < 4; i++)
            #pragma unroll
            for (int j = 0; j < 8; j++)
                red[(kq * 64 + pos) * 33 + i * 8 + j] = cacc[i][j];
        __syncthreads();

        if (tid < 64) {
            const int pqg = tid >> 3;
            const int peg = tid & 7;
            const int b   = bh >> 4;
            const int h   = bh & 15;
            #pragma unroll
            for (int i = 0; i < 4; i++) {
                float o[8];
                #pragma unroll
                for (int j = 0; j < 8; j++) {
                    o[j] = red[(0 * 64 + tid) * 33 + i * 8 + j]
                         + red[(1 * 64 + tid) * 33 + i * 8 + j]
                         + red[(2 * 64 + tid) * 33 + i * 8 + j]
                         + red[(3 * 64 + tid) * 33 + i * 8 + j];
                }
                size_t off = ((size_t)b * SS + q0 + pqg * 4 + i) * DD + h * DH + peg * 8;
                __align__(16) __nv_bfloat16 hb[8], lb[8];
                #pragma unroll
                for (int j = 0; j < 8; j++) {
                    hb[j] = __float2bfloat16(o[j]);
                    lb[j] = __float2bfloat16(o[j] - __bfloat162float(hb[j]));
                }
                *(uint4*)(g_cx_hi + off) = *(uint4*)hb;
                *(uint4*)(g_cx_lo + off) = *(uint4*)lb;
            }
        }
    }
}

// ============================================================
extern "C" void kernel_launch(void* const* d_in, const int* in_sizes, int n_in,
                              void* d_out, int out_size)
{
    const float* q  = (const float*)d_in[0];
    const float* k  = (const float*)d_in[1];
    const float* v  = (const float*)d_in[2];
    const float* Wq = (const float*)d_in[3];
    const float* bq = (const float*)d_in[4];
    const float* Wk = (const float*)d_in[5];
    const float* bk = (const float*)d_in[6];
    const float* Wv = (const float*)d_in[7];
    const float* bv = (const float*)d_in[8];
    const float* Wo = (const float*)d_in[9];
    const float* bo = (const float*)d_in[10];

    float* out   = (float*)d_out;
    float* score = out + (size_t)BB * SS * DD;

    const int attn_smem = (64 * QS_STR + 64 * KT_STR + 32 * SC_STR) * (int)sizeof(float);
    const int gemm_smem = 2 * STAGE_B;   // 147456 B
    cudaFuncSetAttribute(attn_kernel,
                         cudaFuncAttributeMaxDynamicSharedMemorySize, attn_smem);
    cudaFuncSetAttribute(gemm_bf16_kernel,
                         cudaFuncAttributeMaxDynamicSharedMemorySize, gemm_smem);

    __nv_bfloat16 *qhi, *qlo, *khi, *klo, *vhi, *vlo;
    __nv_bfloat16 *wqh, *wql, *wkh, *wkl, *wvh, *wvl, *woh, *wol, *cxh, *cxl;
    float *pqh, *pkh, *pvh;
    cudaGetSymbolAddress((void**)&qhi, g_q_hi);  cudaGetSymbolAddress((void**)&qlo, g_q_lo);
    cudaGetSymbolAddress((void**)&khi, g_k_hi);  cudaGetSymbolAddress((void**)&klo, g_k_lo);
    cudaGetSymbolAddress((void**)&vhi, g_v_hi);  cudaGetSymbolAddress((void**)&vlo, g_v_lo);
    cudaGetSymbolAddress((void**)&wqh, g_wq_hi); cudaGetSymbolAddress((void**)&wql, g_wq_lo);
    cudaGetSymbolAddress((void**)&wkh, g_wk_hi); cudaGetSymbolAddress((void**)&wkl, g_wk_lo);
    cudaGetSymbolAddress((void**)&wvh, g_wv_hi); cudaGetSymbolAddress((void**)&wvl, g_wv_lo);
    cudaGetSymbolAddress((void**)&woh, g_wo_hi); cudaGetSymbolAddress((void**)&wol, g_wo_lo);
    cudaGetSymbolAddress((void**)&cxh, g_cx_hi); cudaGetSymbolAddress((void**)&cxl, g_cx_lo);
    cudaGetSymbolAddress((void**)&pqh, g_qh);
    cudaGetSymbolAddress((void**)&pkh, g_kh);
    cudaGetSymbolAddress((void**)&pvh, g_vh);

    // 1) convert activations + weights to bf16 hi/lo
    cvt_split_kernel<<<MTOT * DD / 1024, 256>>>(q, qhi, qlo);
    cvt_split_kernel<<<MTOT * DD / 1024, 256>>>(k, khi, klo);
    cvt_split_kernel<<<MTOT * DD / 1024, 256>>>(v, vhi, vlo);
    {
        dim3 g(32, 32), b(32, 8);
        cvt_wt_kernel<<<g, b>>>(Wq, wqh, wql, 1);
        cvt_wt_kernel<<<g, b>>>(Wk, wkh, wkl, 1);
        cvt_wt_kernel<<<g, b>>>(Wv, wvh, wvl, 1);
        cvt_wt_kernel<<<g, b>>>(Wo, woh, wol, 0);
    }

    // 2) QKV projections (tensor cores via mma.sync)
    {
        dim3 g(MTOT / 128, DD / 128);
        gemm_bf16_kernel<<<g, 256, gemm_smem>>>(qhi, qlo, wqh, wql, bq, pqh, 0);
        gemm_bf16_kernel<<<g, 256, gemm_smem>>>(khi, klo, wkh, wkl, bk, pkh, 0);
        gemm_bf16_kernel<<<g, 256, gemm_smem>>>(vhi, vlo, wvh, wvl, bv, pvh, 0);
    }

    // 3) fused attention
    {
        dim3 g(SS / 32, BB * HH);
        attn_kernel<<<g, 256, attn_smem>>>(score);
    }

    // 4) output projection (tensor cores via mma.sync)
    {
        dim3 g(MTOT / 128, DD / 128);
        gemm_bf16_kernel<<<g, 256, gemm_smem>>>(cxh, cxl, woh, wol, bo, out, 1);
    }
}

// round 5
// speedup vs baseline: 2.3939x; 1.4747x over previous
#include <cuda_runtime.h>
#include <cuda_bf16.h>
#include <cstdint>

#define BB 4
#define SS 1024
#define DD 1024
#define HH 16
#define DH 64
#define MTOT (BB * SS)          // 4096

// ================= scratch (static device memory; no allocs) =================
__device__ __nv_bfloat16 g_q_hi[MTOT * DD], g_q_lo[MTOT * DD];
__device__ __nv_bfloat16 g_k_hi[MTOT * DD], g_k_lo[MTOT * DD];
__device__ __nv_bfloat16 g_v_hi[MTOT * DD], g_v_lo[MTOT * DD];
__device__ __nv_bfloat16 g_wq_hi[DD * DD], g_wq_lo[DD * DD];   // W^T [n][k]
__device__ __nv_bfloat16 g_wk_hi[DD * DD], g_wk_lo[DD * DD];
__device__ __nv_bfloat16 g_wv_hi[DD * DD], g_wv_lo[DD * DD];
__device__ __nv_bfloat16 g_wo_hi[DD * DD], g_wo_lo[DD * DD];
// projected heads
__device__ __nv_bfloat16 g_qph[BB * HH * SS * DH], g_qpl[BB * HH * SS * DH]; // [B,H,S,dh]
__device__ __nv_bfloat16 g_kph[BB * HH * SS * DH], g_kpl[BB * HH * SS * DH];
__device__ __nv_bfloat16 g_vth[BB * HH * DH * SS], g_vtl[BB * HH * DH * SS]; // [B,H,dh,S]
__device__ __nv_bfloat16 g_cx_hi[MTOT * DD], g_cx_lo[MTOT * DD];             // ctx [m][1024]

// ================= helpers =================
static __device__ __forceinline__ uint32_t smem_u32(const void* p) {
    uint32_t a;
    asm("{ .reg .u64 t; cvta.to.shared.u64 t, %1; cvt.u32.u64 %0, t; }"
        : "=r"(a) : "l"(p));
    return a;
}

#define CP_ASYNC16(dst, src) \
    asm volatile("cp.async.cg.shared.global [%0], [%1], 16;" \
                 :: "r"(dst), "l"(src) : "memory")
#define CP_COMMIT()  asm volatile("cp.async.commit_group;" ::: "memory")
#define CP_WAIT(n)   asm volatile("cp.async.wait_group %0;" :: "n"(n) : "memory")

#define LDSM_X4(r, a) \
    asm volatile("ldmatrix.sync.aligned.m8n8.x4.shared.b16 {%0,%1,%2,%3}, [%4];" \
                 : "=r"((r)[0]), "=r"((r)[1]), "=r"((r)[2]), "=r"((r)[3]) : "r"(a))
#define LDSM_X2(r, a) \
    asm volatile("ldmatrix.sync.aligned.m8n8.x2.shared.b16 {%0,%1}, [%2];" \
                 : "=r"((r)[0]), "=r"((r)[1]) : "r"(a))
#define MMA16816(c, a, b) \
    asm volatile("mma.sync.aligned.m16n8k16.row.col.f32.bf16.bf16.f32 " \
                 "{%0,%1,%2,%3}, {%4,%5,%6,%7}, {%8,%9}, {%0,%1,%2,%3};" \
                 : "+f"((c)[0]), "+f"((c)[1]), "+f"((c)[2]), "+f"((c)[3]) \
                 : "r"((a)[0]), "r"((a)[1]), "r"((a)[2]), "r"((a)[3]), \
                   "r"((b)[0]), "r"((b)[1]))

static __device__ __forceinline__ uint32_t pack_bf2(float x, float y) {
    __nv_bfloat16 a = __float2bfloat16(x), b = __float2bfloat16(y);
    uint16_t ua = *(uint16_t*)&a, ub = *(uint16_t*)&b;
    return (uint32_t)ua | ((uint32_t)ub << 16);
}
// split a float pair into packed hi / packed lo bf16x2
static __device__ __forceinline__ void split_bf2(float x, float y,
                                                 uint32_t& hi, uint32_t& lo) {
    __nv_bfloat16 hx = __float2bfloat16(x), hy = __float2bfloat16(y);
    float rx = x - __bfloat162float(hx);
    float ry = y - __bfloat162float(hy);
    uint16_t ux = *(uint16_t*)&hx, uy = *(uint16_t*)&hy;
    hi = (uint32_t)ux | ((uint32_t)uy << 16);
    lo = pack_bf2(rx, ry);
}

// ================= conversion kernels =================
__global__ __launch_bounds__(256) void cvt_split_kernel(
    const float* __restrict__ src, __nv_bfloat16* __restrict__ hi,
    __nv_bfloat16* __restrict__ lo)
{
    int i = (blockIdx.x * 256 + threadIdx.x) * 4;
    float4 f = *(const float4*)(src + i);
    __nv_bfloat16 h[4], l[4];
    float v[4] = {f.x, f.y, f.z, f.w};
    #pragma unroll
    for (int j = 0; j < 4; j++) {
        h[j] = __float2bfloat16(v[j]);
        l[j] = __float2bfloat16(v[j] - __bfloat162float(h[j]));
    }
    *(uint2*)(hi + i) = *(uint2*)h;
    *(uint2*)(lo + i) = *(uint2*)l;
}

// weight transpose + split: logical W[k][n] -> Wt[n][k] bf16 hi/lo
__global__ __launch_bounds__(256) void cvt_wt_kernel(
    const float* __restrict__ W, __nv_bfloat16* __restrict__ hi,
    __nv_bfloat16* __restrict__ lo, int interleaved)
{
    __shared__ float t[32][33];
    const int tx = threadIdx.x, ty = threadIdx.y;
    const int k0 = blockIdx.x * 32, n0 = blockIdx.y * 32;

    #pragma unroll
    for (int i = 0; i < 4; i++) {
        int k = k0 + ty + i * 8;
        int n = n0 + tx;
        size_t a = interleaved ? ((size_t)(n >> 6) * 65536 + (size_t)k * 64 + (n & 63))
                               : ((size_t)k * 1024 + n);
        t[ty + i * 8][tx] = W[a];
    }
    __syncthreads();
    #pragma unroll
    for (int i = 0; i < 4; i++) {
        int n = n0 + ty + i * 8;
        int k = k0 + tx;
        float v = t[tx][ty + i * 8];
        __nv_bfloat16 h = __float2bfloat16(v);
        hi[(size_t)n * 1024 + k] = h;
        lo[(size_t)n * 1024 + k] = __float2bfloat16(v - __bfloat162float(h));
    }
}

// ================= mma.sync bf16-split GEMM =================
//   mode 0: out bf16 hi/lo at [B,H,S,dh]     (q,k head projections)
//   mode 2: out bf16 hi/lo at [B,H,dh,S]     (v head projection, transposed)
//   mode 1: out fp32 row-major [m][n]        (final out-proj)
#define KSTRIDE 72                       // padded bf16 row stride (144 B)
#define TILE_B  (128 * KSTRIDE * 2)      // 18432 B per tile
#define OFF_AH  0
#define OFF_AL  (TILE_B)
#define OFF_BH  (2 * TILE_B)
#define OFF_BL  (3 * TILE_B)
#define STAGE_B (4 * TILE_B)             // 73728 B

__global__ __launch_bounds__(256) void gemm_bf16_kernel(
    const __nv_bfloat16* __restrict__ Ahi, const __nv_bfloat16* __restrict__ Alo,
    const __nv_bfloat16* __restrict__ Bhi, const __nv_bfloat16* __restrict__ Blo,
    const float* __restrict__ bias, float* __restrict__ Cf,
    __nv_bfloat16* __restrict__ Ch, __nv_bfloat16* __restrict__ Cl, int mode)
{
    extern __shared__ char sm[];
    const uint32_t smb = smem_u32(sm);

    const int tid    = threadIdx.x;
    const int lane   = tid & 31;
    const int warp   = tid >> 5;
    const int warp_m = warp >> 2;
    const int warp_n = warp & 3;
    const int m0 = blockIdx.x * 128;
    const int n0 = blockIdx.y * 128;

    const uint32_t aoff = ((warp_m * 64 + (lane & 15)) * KSTRIDE + ((lane >> 4) * 8)) * 2;
    const uint32_t boff = ((warp_n * 32 + (lane & 7)) * KSTRIDE + (((lane >> 3) & 1) * 8)) * 2;

    float acc[4][4][4] = {};

    auto issue = [&](int c) {
        const uint32_t sb = smb + (c & 1) * STAGE_B;
        const int k0 = c * 64;
        #pragma unroll
        for (int i = 0; i < 4; i++) {
            int lin = tid + i * 256;
            int row = lin >> 3;
            int cg  = lin & 7;
            uint32_t so = (uint32_t)(row * KSTRIDE * 2 + cg * 16);
            size_t ga = (size_t)(m0 + row) * DD + k0 + cg * 8;
            size_t gb = (size_t)(n0 + row) * DD + k0 + cg * 8;
            CP_ASYNC16(sb + OFF_AH + so, Ahi + ga);
            CP_ASYNC16(sb + OFF_AL + so, Alo + ga);
            CP_ASYNC16(sb + OFF_BH + so, Bhi + gb);
            CP_ASYNC16(sb + OFF_BL + so, Blo + gb);
        }
    };

    issue(0);
    CP_COMMIT();

    for (int c = 0; c < DD / 64; c++) {
        if (c + 1 < DD / 64) {
            issue(c + 1);
            CP_COMMIT();
            CP_WAIT(1);
        } else {
            CP_WAIT(0);
        }
        __syncthreads();

        const uint32_t sb = smb + (c & 1) * STAGE_B;
        #pragma unroll
        for (int kk = 0; kk < 4; kk++) {
            const uint32_t kby = kk * 32;
            uint32_t ah[4][4], al[4][4];
            #pragma unroll
            for (int mf = 0; mf < 4; mf++) {
                uint32_t ra = sb + aoff + (uint32_t)(mf * 16 * KSTRIDE * 2) + kby;
                LDSM_X4(ah[mf], ra + OFF_AH);
                LDSM_X4(al[mf], ra + OFF_AL);
            }
            uint32_t bh[4][2], bl[4][2];
            #pragma unroll
            for (int nf = 0; nf < 4; nf++) {
                uint32_t rb = sb + boff + (uint32_t)(nf * 8 * KSTRIDE * 2) + kby;
                LDSM_X2(bh[nf], rb + OFF_BH);
                LDSM_X2(bl[nf], rb + OFF_BL);
            }
            #pragma unroll
            for (int mf = 0; mf < 4; mf++)
                #pragma unroll
                for (int nf = 0; nf < 4; nf++) {
                    MMA16816(acc[mf][nf], ah[mf], bh[nf]);
                    MMA16816(acc[mf][nf], ah[mf], bl[nf]);
                    MMA16816(acc[mf][nf], al[mf], bh[nf]);
                }
        }
        __syncthreads();
    }

    // ---- epilogue ----
    const int lr = lane >> 2;
    const int lc = (lane & 3) * 2;
    #pragma unroll
    for (int mf = 0; mf < 4; mf++) {
        #pragma unroll
        for (int nf = 0; nf < 4; nf++) {
            int n = n0 + warp_n * 32 + nf * 8 + lc;
            float bv0 = bias[n], bv1 = bias[n + 1];
            #pragma unroll
            for (int half = 0; half < 2; half++) {
                int m = m0 + warp_m * 64 + mf * 16 + lr + half * 8;
                float x = acc[mf][nf][half * 2 + 0] + bv0;
                float y = acc[mf][nf][half * 2 + 1] + bv1;
                if (mode == 1) {
                    *(float2*)(Cf + (size_t)m * DD + n) = make_float2(x, y);
                } else {
                    uint32_t phi, plo;
                    split_bf2(x, y, phi, plo);
                    int bidx = m >> 10, s = m & 1023;
                    int h = n >> 6, e = n & 63;
                    if (mode == 0) {
                        size_t off = (((size_t)bidx * HH + h) * SS + s) * DH + e;
                        *(uint32_t*)(Ch + off) = phi;
                        *(uint32_t*)(Cl + off) = plo;
                    } else { // mode 2: [B,H,dh,S]
                        size_t off = (((size_t)bidx * HH + h) * DH + e) * SS + s;
                        Ch[off]      = *(__nv_bfloat16*)&phi;
                        Ch[off + SS] = ((__nv_bfloat16*)&phi)[1];
                        Cl[off]      = *(__nv_bfloat16*)&plo;
                        Cl[off + SS] = ((__nv_bfloat16*)&plo)[1];
                    }
                }
            }
        }
    }
}

// ================= tensor-core fused attention =================
//   CTA = (bh, 32-query tile). 256 threads (8 warps).
//   phase1: logits = Q K^T via split-bf16 mma, fp32 into smem
//   phase2: exact softmax + score gmem write
//   phase3: ctx = P V via split-bf16 mma (P converted on the fly), warp key-split
#define ATT_KST 72      // bf16 row stride for q / k tiles (144 B, 16B-aligned)
#define ATT_VST 264     // bf16 row stride for V^T tile (528 B, 16B-aligned)
#define ATT_SCS 1028    // fp32 logits row stride

#define AOFF_QH 0
#define AOFF_QL 4608
#define AOFF_KB 9216                     // K chunk hi (36864) + lo (36864); reused
#define AOFF_KL (AOFF_KB + 36864)
#define AOFF_VH AOFF_KB                  // V^T hi 64*528 = 33792
#define AOFF_VL (AOFF_KB + 33792)
#define AOFF_RED AOFF_KB                 // reduce buffer 8*32*64*4 = 65536
#define AOFF_SC (AOFF_KB + 73728)        // 82944; fp32 logits 32*1028*4 = 131584
#define ATT_SMEM (AOFF_SC + 32 * ATT_SCS * 4)   // 214528 B

__global__ __launch_bounds__(256) void attn_kernel(float* __restrict__ score_out)
{
    extern __shared__ char sm[];
    const uint32_t smb = smem_u32(sm);
    float* sc = (float*)(sm + AOFF_SC);

    const int bh  = blockIdx.y;
    const int q0  = blockIdx.x * 32;
    const int tid = threadIdx.x;
    const int lane = tid & 31;
    const int w    = tid >> 5;

    const __nv_bfloat16* qph = g_qph + (size_t)bh * SS * DH;
    const __nv_bfloat16* qpl = g_qpl + (size_t)bh * SS * DH;
    const __nv_bfloat16* kph = g_kph + (size_t)bh * SS * DH;
    const __nv_bfloat16* kpl = g_kpl + (size_t)bh * SS * DH;
    const __nv_bfloat16* vth = g_vth + (size_t)bh * DH * SS;
    const __nv_bfloat16* vtl = g_vtl + (size_t)bh * DH * SS;

    // ---- load q tile (32 x 64) hi/lo ----
    {
        int row = tid >> 3, grp = tid & 7;
        size_t src = (size_t)(q0 + row) * DH + grp * 8;
        uint32_t dst = (uint32_t)(row * ATT_KST * 2 + grp * 16);
        *(uint4*)(sm + AOFF_QH + dst) = *(const uint4*)(qph + src);
        *(uint4*)(sm + AOFF_QL + dst) = *(const uint4*)(qpl + src);
    }
    __syncthreads();

    // ldmatrix lane offsets
    const uint32_t a_off = ((lane & 15) * ATT_KST + (lane >> 4) * 8) * 2;
    const uint32_t b_off = (((lane & 7)) * ATT_KST + ((lane >> 3) & 1) * 8) * 2;
    const uint32_t bv_off = (((lane & 7)) * ATT_VST + ((lane >> 3) & 1) * 8) * 2;

    // ---- phase 1: logits ----
    for (int c0 = 0; c0 < SS; c0 += 256) {
        // load K chunk (256 x 64) hi/lo
        #pragma unroll
        for (int i = 0; i < 8; i++) {
            int lin = tid + i * 256;
            int row = lin >> 3, grp = lin & 7;
            size_t src = (size_t)(c0 + row) * DH + grp * 8;
            uint32_t dst = (uint32_t)(row * ATT_KST * 2 + grp * 16);
            *(uint4*)(sm + AOFF_KB + dst) = *(const uint4*)(kph + src);
            *(uint4*)(sm + AOFF_KL + dst) = *(const uint4*)(kpl + src);
        }
        __syncthreads();

        float acc[2][4][4] = {};
        #pragma unroll
        for (int kk = 0; kk < 4; kk++) {
            const uint32_t kby = kk * 32;
            uint32_t ah[2][4], al[2][4];
            #pragma unroll
            for (int mf = 0; mf < 2; mf++) {
                uint32_t ra = smb + a_off + (uint32_t)(mf * 16 * ATT_KST * 2) + kby;
                LDSM_X4(ah[mf], ra + AOFF_QH);
                LDSM_X4(al[mf], ra + AOFF_QL);
            }
            #pragma unroll
            for (int nf = 0; nf < 4; nf++) {
                uint32_t rb = smb + b_off
                            + (uint32_t)((w * 32 + nf * 8) * ATT_KST * 2) + kby;
                uint32_t bh[2], bl[2];
                LDSM_X2(bh, rb + AOFF_KB);
                LDSM_X2(bl, rb + AOFF_KL);
                #pragma unroll
                for (int mf = 0; mf < 2; mf++) {
                    MMA16816(acc[mf][nf], ah[mf], bh);
                    MMA16816(acc[mf][nf], ah[mf], bl);
                    MMA16816(acc[mf][nf], al[mf], bh);
                }
            }
        }
        // store logits to sc (scaled)
        #pragma unroll
        for (int mf = 0; mf < 2; mf++)
            #pragma unroll
            for (int nf = 0; nf < 4; nf++) {
                int row = mf * 16 + (lane >> 2);
                int key = c0 + w * 32 + nf * 8 + (lane & 3) * 2;
                *(float2*)&sc[row * ATT_SCS + key] =
                    make_float2(acc[mf][nf][0] * 0.125f, acc[mf][nf][1] * 0.125f);
                *(float2*)&sc[(row + 8) * ATT_SCS + key] =
                    make_float2(acc[mf][nf][2] * 0.125f, acc[mf][nf][3] * 0.125f);
            }
        __syncthreads();
    }

    // ---- phase 2: exact softmax + score write ----
    {
        for (int rr = 0; rr < 4; rr++) {
            int r = w * 4 + rr;
            float* row = sc + r * ATT_SCS;
            float mx = row[lane];
            #pragma unroll
            for (int i = 1; i < 32; i++) mx = fmaxf(mx, row[i * 32 + lane]);
            #pragma unroll
            for (int o = 16; o; o >>= 1) mx = fmaxf(mx, __shfl_xor_sync(0xFFFFFFFFu, mx, o));

            float sum = 0.f;
            #pragma unroll
            for (int i = 0; i < 32; i++) {
                float e = __expf(row[i * 32 + lane] - mx);
                row[i * 32 + lane] = e;
                sum += e;
            }
            #pragma unroll
            for (int o = 16; o; o >>= 1) sum += __shfl_xor_sync(0xFFFFFFFFu, sum, o);
            float inv = 1.f / sum;

            float* g = score_out + ((size_t)bh * SS + q0 + r) * SS;
            #pragma unroll
            for (int i = 0; i < 32; i++) {
                float p = row[i * 32 + lane] * inv;
                row[i * 32 + lane] = p;
                __stcs(&g[i * 32 + lane], p);
            }
        }
    }
    __syncthreads();

    // ---- phase 3: ctx = P @ V ----
    {
        float acc[2][8][4] = {};
        for (int c0 = 0; c0 < SS; c0 += 256) {
            // load V^T chunk (64 e-rows x 256 keys) hi/lo
            #pragma unroll
            for (int i = 0; i < 8; i++) {
                int lin = tid + i * 256;
                int e = lin >> 5, g = lin & 31;
                size_t src = (size_t)e * SS + c0 + g * 8;
                uint32_t dst = (uint32_t)(e * ATT_VST * 2 + g * 16);
                *(uint4*)(sm + AOFF_VH + dst) = *(const uint4*)(vth + src);
                *(uint4*)(sm + AOFF_VL + dst) = *(const uint4*)(vtl + src);
            }
            __syncthreads();

            #pragma unroll
            for (int kk = 0; kk < 2; kk++) {
                const int kb = c0 + w * 32 + kk * 16;   // this warp's key base
                // build P A-fragments (hi/lo) from fp32 probs in sc
                uint32_t pa_h[2][4], pa_l[2][4];
                #pragma unroll
                for (int mf = 0; mf < 2; mf++) {
                    int r0 = mf * 16 + (lane >> 2);
                    int cc = kb + (lane & 3) * 2;
                    float2 p00 = *(float2*)&sc[r0 * ATT_SCS + cc];
                    float2 p10 = *(float2*)&sc[(r0 + 8) * ATT_SCS + cc];
                    float2 p01 = *(float2*)&sc[r0 * ATT_SCS + cc + 8];
                    float2 p11 = *(float2*)&sc[(r0 + 8) * ATT_SCS + cc + 8];
                    split_bf2(p00.x, p00.y, pa_h[mf][0], pa_l[mf][0]);
                    split_bf2(p10.x, p10.y, pa_h[mf][1], pa_l[mf][1]);
                    split_bf2(p01.x, p01.y, pa_h[mf][2], pa_l[mf][2]);
                    split_bf2(p11.x, p11.y, pa_h[mf][3], pa_l[mf][3]);
                }
                const uint32_t kwby = (uint32_t)((w * 32 + kk * 16) * 2); // key byte off in V^T row
                #pragma unroll
                for (int nf = 0; nf < 8; nf++) {
                    uint32_t rb = smb + bv_off
                                + (uint32_t)(nf * 8 * ATT_VST * 2) + kwby;
                    uint32_t bh[2], bl[2];
                    LDSM_X2(bh, rb + AOFF_VH);
                    LDSM_X2(bl, rb + AOFF_VL);
                    #pragma unroll
                    for (int mf = 0; mf < 2; mf++) {
                        MMA16816(acc[mf][nf], pa_h[mf], bh);
                        MMA16816(acc[mf][nf], pa_h[mf], bl);
                        MMA16816(acc[mf][nf], pa_l[mf], bh);
                    }
                }
            }
            __syncthreads();
        }

        // cross-warp reduce (8 partials of ctx[32][64])
        float* red = (float*)(sm + AOFF_RED);
        #pragma unroll
        for (int mf = 0; mf < 2; mf++)
            #pragma unroll
            for (int nf = 0; nf < 8; nf++) {
                int row = mf * 16 + (lane >> 2);
                int col = nf * 8 + (lane & 3) * 2;
                *(float2*)&red[w * 2048 + row * 64 + col] =
                    make_float2(acc[mf][nf][0], acc[mf][nf][1]);
                *(float2*)&red[w * 2048 + (row + 8) * 64 + col] =
                    make_float2(acc[mf][nf][2], acc[mf][nf][3]);
            }
        __syncthreads();

        {
            const int row = tid >> 3;
            const int cg  = (tid & 7) * 8;
            float o[8];
            #pragma unroll
            for (int j = 0; j < 8; j++) {
                float s = 0.f;
                #pragma unroll
                for (int ww = 0; ww < 8; ww++)
                    s += red[ww * 2048 + row * 64 + cg + j];
                o[j] = s;
            }
            const int b = bh >> 4;
            const int h = bh & 15;
            size_t off = ((size_t)b * SS + q0 + row) * DD + h * DH + cg;
            __align__(16) __nv_bfloat16 hb[8], lb[8];
            #pragma unroll
            for (int j = 0; j < 8; j++) {
                hb[j] = __float2bfloat16(o[j]);
                lb[j] = __float2bfloat16(o[j] - __bfloat162float(hb[j]));
            }
            *(uint4*)(g_cx_hi + off) = *(uint4*)hb;
            *(uint4*)(g_cx_lo + off) = *(uint4*)lb;
        }
    }
}

// ============================================================
extern "C" void kernel_launch(void* const* d_in, const int* in_sizes, int n_in,
                              void* d_out, int out_size)
{
    const float* q  = (const float*)d_in[0];
    const float* k  = (const float*)d_in[1];
    const float* v  = (const float*)d_in[2];
    const float* Wq = (const float*)d_in[3];
    const float* bq = (const float*)d_in[4];
    const float* Wk = (const float*)d_in[5];
    const float* bk = (const float*)d_in[6];
    const float* Wv = (const float*)d_in[7];
    const float* bv = (const float*)d_in[8];
    const float* Wo = (const float*)d_in[9];
    const float* bo = (const float*)d_in[10];

    float* out   = (float*)d_out;
    float* score = out + (size_t)BB * SS * DD;

    const int gemm_smem = 2 * STAGE_B;   // 147456 B
    cudaFuncSetAttribute(attn_kernel,
                         cudaFuncAttributeMaxDynamicSharedMemorySize, ATT_SMEM);
    cudaFuncSetAttribute(gemm_bf16_kernel,
                         cudaFuncAttributeMaxDynamicSharedMemorySize, gemm_smem);

    __nv_bfloat16 *qhi, *qlo, *khi, *klo, *vhi, *vlo;
    __nv_bfloat16 *wqh, *wql, *wkh, *wkl, *wvh, *wvl, *woh, *wol, *cxh, *cxl;
    __nv_bfloat16 *qph, *qpl, *kph, *kpl, *vth, *vtl;
    cudaGetSymbolAddress((void**)&qhi, g_q_hi);  cudaGetSymbolAddress((void**)&qlo, g_q_lo);
    cudaGetSymbolAddress((void**)&khi, g_k_hi);  cudaGetSymbolAddress((void**)&klo, g_k_lo);
    cudaGetSymbolAddress((void**)&vhi, g_v_hi);  cudaGetSymbolAddress((void**)&vlo, g_v_lo);
    cudaGetSymbolAddress((void**)&wqh, g_wq_hi); cudaGetSymbolAddress((void**)&wql, g_wq_lo);
    cudaGetSymbolAddress((void**)&wkh, g_wk_hi); cudaGetSymbolAddress((void**)&wkl, g_wk_lo);
    cudaGetSymbolAddress((void**)&wvh, g_wv_hi); cudaGetSymbolAddress((void**)&wvl, g_wv_lo);
    cudaGetSymbolAddress((void**)&woh, g_wo_hi); cudaGetSymbolAddress((void**)&wol, g_wo_lo);
    cudaGetSymbolAddress((void**)&cxh, g_cx_hi); cudaGetSymbolAddress((void**)&cxl, g_cx_lo);
    cudaGetSymbolAddress((void**)&qph, g_qph);   cudaGetSymbolAddress((void**)&qpl, g_qpl);
    cudaGetSymbolAddress((void**)&kph, g_kph);   cudaGetSymbolAddress((void**)&kpl, g_kpl);
    cudaGetSymbolAddress((void**)&vth, g_vth);   cudaGetSymbolAddress((void**)&vtl, g_vtl);

    // 1) convert activations + weights to bf16 hi/lo
    cvt_split_kernel<<<MTOT * DD / 1024, 256>>>(q, qhi, qlo);
    cvt_split_kernel<<<MTOT * DD / 1024, 256>>>(k, khi, klo);
    cvt_split_kernel<<<MTOT * DD / 1024, 256>>>(v, vhi, vlo);
    {
        dim3 g(32, 32), b(32, 8);
        cvt_wt_kernel<<<g, b>>>(Wq, wqh, wql, 1);
        cvt_wt_kernel<<<g, b>>>(Wk, wkh, wkl, 1);
        cvt_wt_kernel<<<g, b>>>(Wv, wvh, wvl, 1);
        cvt_wt_kernel<<<g, b>>>(Wo, woh, wol, 0);
    }

    // 2) QKV projections -> bf16 heads (V transposed)
    {
        dim3 g(MTOT / 128, DD / 128);
        gemm_bf16_kernel<<<g, 256, gemm_smem>>>(qhi, qlo, wqh, wql, bq,
                                                nullptr, qph, qpl, 0);
        gemm_bf16_kernel<<<g, 256, gemm_smem>>>(khi, klo, wkh, wkl, bk,
                                                nullptr, kph, kpl, 0);
        gemm_bf16_kernel<<<g, 256, gemm_smem>>>(vhi, vlo, wvh, wvl, bv,
                                                nullptr, vth, vtl, 2);
    }

    // 3) tensor-core fused attention
    {
        dim3 g(SS / 32, BB * HH);
        attn_kernel<<<g, 256, ATT_SMEM>>>(score);
    }

    // 4) output projection (fp32 out)
    {
        dim3 g(MTOT / 128, DD / 128);
        gemm_bf16_kernel<<<g, 256, gemm_smem>>>(cxh, cxl, woh, wol, bo,
                                                out, nullptr, nullptr, 1);
    }
}

// round 6
// speedup vs baseline: 2.6536x; 1.1085x over previous
#include <cuda_runtime.h>
#include <cuda_bf16.h>
#include <cstdint>

#define BB 4
#define SS 1024
#define DD 1024
#define HH 16
#define DH 64
#define MTOT (BB * SS)          // 4096

// ================= scratch (static device memory; no allocs) =================
__device__ __nv_bfloat16 g_q_hi[MTOT * DD], g_q_lo[MTOT * DD];
__device__ __nv_bfloat16 g_k_hi[MTOT * DD], g_k_lo[MTOT * DD];
__device__ __nv_bfloat16 g_v_hi[MTOT * DD], g_v_lo[MTOT * DD];
__device__ __nv_bfloat16 g_wq_hi[DD * DD], g_wq_lo[DD * DD];   // W^T [n][k]
__device__ __nv_bfloat16 g_wk_hi[DD * DD], g_wk_lo[DD * DD];
__device__ __nv_bfloat16 g_wv_hi[DD * DD], g_wv_lo[DD * DD];
__device__ __nv_bfloat16 g_wo_hi[DD * DD], g_wo_lo[DD * DD];
// projected heads
__device__ __nv_bfloat16 g_qph[BB * HH * SS * DH], g_qpl[BB * HH * SS * DH]; // [B,H,S,dh]
__device__ __nv_bfloat16 g_kph[BB * HH * SS * DH], g_kpl[BB * HH * SS * DH];
__device__ __nv_bfloat16 g_vth[BB * HH * DH * SS], g_vtl[BB * HH * DH * SS]; // [B,H,dh,S]
__device__ __nv_bfloat16 g_cx_hi[MTOT * DD], g_cx_lo[MTOT * DD];             // ctx [m][1024]

// ================= helpers =================
static __device__ __forceinline__ uint32_t smem_u32(const void* p) {
    uint32_t a;
    asm("{ .reg .u64 t; cvta.to.shared.u64 t, %1; cvt.u32.u64 %0, t; }"
        : "=r"(a) : "l"(p));
    return a;
}

#define CP_ASYNC16(dst, src) \
    asm volatile("cp.async.cg.shared.global [%0], [%1], 16;" \
                 :: "r"(dst), "l"(src) : "memory")
#define CP_COMMIT()  asm volatile("cp.async.commit_group;" ::: "memory")
#define CP_WAIT(n)   asm volatile("cp.async.wait_group %0;" :: "n"(n) : "memory")

#define LDSM_X4(r, a) \
    asm volatile("ldmatrix.sync.aligned.m8n8.x4.shared.b16 {%0,%1,%2,%3}, [%4];" \
                 : "=r"((r)[0]), "=r"((r)[1]), "=r"((r)[2]), "=r"((r)[3]) : "r"(a))
#define LDSM_X2(r, a) \
    asm volatile("ldmatrix.sync.aligned.m8n8.x2.shared.b16 {%0,%1}, [%2];" \
                 : "=r"((r)[0]), "=r"((r)[1]) : "r"(a))
#define MMA16816(c, a, b) \
    asm volatile("mma.sync.aligned.m16n8k16.row.col.f32.bf16.bf16.f32 " \
                 "{%0,%1,%2,%3}, {%4,%5,%6,%7}, {%8,%9}, {%0,%1,%2,%3};" \
                 : "+f"((c)[0]), "+f"((c)[1]), "+f"((c)[2]), "+f"((c)[3]) \
                 : "r"((a)[0]), "r"((a)[1]), "r"((a)[2]), "r"((a)[3]), \
                   "r"((b)[0]), "r"((b)[1]))

static __device__ __forceinline__ uint32_t pack_bf2(float x, float y) {
    __nv_bfloat16 a = __float2bfloat16(x), b = __float2bfloat16(y);
    uint16_t ua = *(uint16_t*)&a, ub = *(uint16_t*)&b;
    return (uint32_t)ua | ((uint32_t)ub << 16);
}
static __device__ __forceinline__ void split_bf2(float x, float y,
                                                 uint32_t& hi, uint32_t& lo) {
    __nv_bfloat16 hx = __float2bfloat16(x), hy = __float2bfloat16(y);
    float rx = x - __bfloat162float(hx);
    float ry = y - __bfloat162float(hy);
    uint16_t ux = *(uint16_t*)&hx, uy = *(uint16_t*)&hy;
    hi = (uint32_t)ux | ((uint32_t)uy << 16);
    lo = pack_bf2(rx, ry);
}

// ================= conversion kernels =================
__global__ __launch_bounds__(256) void cvt_split_kernel(
    const float* __restrict__ src, __nv_bfloat16* __restrict__ hi,
    __nv_bfloat16* __restrict__ lo)
{
    int i = (blockIdx.x * 256 + threadIdx.x) * 4;
    float4 f = *(const float4*)(src + i);
    __nv_bfloat16 h[4], l[4];
    float v[4] = {f.x, f.y, f.z, f.w};
    #pragma unroll
    for (int j = 0; j < 4; j++) {
        h[j] = __float2bfloat16(v[j]);
        l[j] = __float2bfloat16(v[j] - __bfloat162float(h[j]));
    }
    *(uint2*)(hi + i) = *(uint2*)h;
    *(uint2*)(lo + i) = *(uint2*)l;
}

__global__ __launch_bounds__(256) void cvt_wt_kernel(
    const float* __restrict__ W, __nv_bfloat16* __restrict__ hi,
    __nv_bfloat16* __restrict__ lo, int interleaved)
{
    __shared__ float t[32][33];
    const int tx = threadIdx.x, ty = threadIdx.y;
    const int k0 = blockIdx.x * 32, n0 = blockIdx.y * 32;

    #pragma unroll
    for (int i = 0; i < 4; i++) {
        int k = k0 + ty + i * 8;
        int n = n0 + tx;
        size_t a = interleaved ? ((size_t)(n >> 6) * 65536 + (size_t)k * 64 + (n & 63))
                               : ((size_t)k * 1024 + n);
        t[ty + i * 8][tx] = W[a];
    }
    __syncthreads();
    #pragma unroll
    for (int i = 0; i < 4; i++) {
        int n = n0 + ty + i * 8;
        int k = k0 + tx;
        float v = t[tx][ty + i * 8];
        __nv_bfloat16 h = __float2bfloat16(v);
        hi[(size_t)n * 1024 + k] = h;
        lo[(size_t)n * 1024 + k] = __float2bfloat16(v - __bfloat162float(h));
    }
}

// ================= mma.sync bf16-split GEMM core =================
//   CTA tile 128m x 64n, K-chunk 32, 2-stage cp.async, 128 threads (4 warps 2m x 2n)
//   mode 0: out bf16 hi/lo at [B,H,S,dh]
//   mode 2: out bf16 hi/lo at [B,H,dh,S] (transposed)
//   mode 1: out fp32 row-major [m][n]
#define GK 40                            // padded bf16 row stride (80 B)
#define G_AH 0
#define G_AL 10240
#define G_BH 20480
#define G_BL 25600
#define G_STAGE 30720                    // per-stage bytes
#define GEMM_SMEM (2 * G_STAGE)          // 61440

static __device__ __forceinline__ void gemm_core(
    const __nv_bfloat16* __restrict__ Ahi, const __nv_bfloat16* __restrict__ Alo,
    const __nv_bfloat16* __restrict__ Bhi, const __nv_bfloat16* __restrict__ Blo,
    const float* __restrict__ bias, float* __restrict__ Cf,
    __nv_bfloat16* __restrict__ Ch, __nv_bfloat16* __restrict__ Cl, int mode,
    char* sm)
{
    const uint32_t smb = smem_u32(sm);
    const int tid    = threadIdx.x;
    const int lane   = tid & 31;
    const int warp   = tid >> 5;         // 0..3
    const int warp_m = warp >> 1;        // 0..1 (64 rows)
    const int warp_n = warp & 1;         // 0..1 (32 cols)
    const int m0 = blockIdx.x * 128;
    const int n0 = blockIdx.y * 64;

    const uint32_t aoff = ((warp_m * 64 + (lane & 15)) * GK + ((lane >> 4) * 8)) * 2;
    const uint32_t boff = ((warp_n * 32 + (lane & 7)) * GK + (((lane >> 3) & 1) * 8)) * 2;

    float acc[4][4][4] = {};

    auto issue = [&](int c) {
        const uint32_t sb = smb + (c & 1) * G_STAGE;
        const int k0 = c * 32;
        #pragma unroll
        for (int j = 0; j < 4; j++) {
            int lin = tid + j * 128;          // 0..511
            int row = lin >> 2;               // 0..127
            int cg  = lin & 3;
            uint32_t so = (uint32_t)(row * 80 + cg * 16);
            size_t ga = (size_t)(m0 + row) * DD + k0 + cg * 8;
            CP_ASYNC16(sb + G_AH + so, Ahi + ga);
            CP_ASYNC16(sb + G_AL + so, Alo + ga);
        }
        #pragma unroll
        for (int j = 0; j < 2; j++) {
            int lin = tid + j * 128;          // 0..255
            int row = lin >> 2;               // 0..63
            int cg  = lin & 3;
            uint32_t so = (uint32_t)(row * 80 + cg * 16);
            size_t gb = (size_t)(n0 + row) * DD + k0 + cg * 8;
            CP_ASYNC16(sb + G_BH + so, Bhi + gb);
            CP_ASYNC16(sb + G_BL + so, Blo + gb);
        }
    };

    issue(0);
    CP_COMMIT();

    for (int c = 0; c < DD / 32; c++) {
        if (c + 1 < DD / 32) {
            issue(c + 1);
            CP_COMMIT();
            CP_WAIT(1);
        } else {
            CP_WAIT(0);
        }
        __syncthreads();

        const uint32_t sb = smb + (c & 1) * G_STAGE;
        #pragma unroll
        for (int kk = 0; kk < 2; kk++) {
            const uint32_t kby = kk * 32;
            uint32_t ah[4][4], al[4][4];
            #pragma unroll
            for (int mf = 0; mf < 4; mf++) {
                uint32_t ra = sb + aoff + (uint32_t)(mf * 16 * 80) + kby;
                LDSM_X4(ah[mf], ra + G_AH);
                LDSM_X4(al[mf], ra + G_AL);
            }
            uint32_t bh[4][2], bl[4][2];
            #pragma unroll
            for (int nf = 0; nf < 4; nf++) {
                uint32_t rb = sb + boff + (uint32_t)(nf * 8 * 80) + kby;
                LDSM_X2(bh[nf], rb + G_BH);
                LDSM_X2(bl[nf], rb + G_BL);
            }
            #pragma unroll
            for (int mf = 0; mf < 4; mf++)
                #pragma unroll
                for (int nf = 0; nf < 4; nf++) {
                    MMA16816(acc[mf][nf], ah[mf], bh[nf]);
                    MMA16816(acc[mf][nf], ah[mf], bl[nf]);
                    MMA16816(acc[mf][nf], al[mf], bh[nf]);
                }
        }
        __syncthreads();
    }

    // ---- epilogue ----
    const int lr = lane >> 2;
    const int lc = (lane & 3) * 2;
    #pragma unroll
    for (int mf = 0; mf < 4; mf++) {
        #pragma unroll
        for (int nf = 0; nf < 4; nf++) {
            int n = n0 + warp_n * 32 + nf * 8 + lc;
            float bv0 = bias[n], bv1 = bias[n + 1];
            #pragma unroll
            for (int half = 0; half < 2; half++) {
                int m = m0 + warp_m * 64 + mf * 16 + lr + half * 8;
                float x = acc[mf][nf][half * 2 + 0] + bv0;
                float y = acc[mf][nf][half * 2 + 1] + bv1;
                if (mode == 1) {
                    *(float2*)(Cf + (size_t)m * DD + n) = make_float2(x, y);
                } else {
                    uint32_t phi, plo;
                    split_bf2(x, y, phi, plo);
                    int bidx = m >> 10, s = m & 1023;
                    int h = n >> 6, e = n & 63;
                    if (mode == 0) {
                        size_t off = (((size_t)bidx * HH + h) * SS + s) * DH + e;
                        *(uint32_t*)(Ch + off) = phi;
                        *(uint32_t*)(Cl + off) = plo;
                    } else { // mode 2: [B,H,dh,S]
                        size_t off = (((size_t)bidx * HH + h) * DH + e) * SS + s;
                        Ch[off]      = *(__nv_bfloat16*)&phi;
                        Ch[off + SS] = ((__nv_bfloat16*)&phi)[1];
                        Cl[off]      = *(__nv_bfloat16*)&plo;
                        Cl[off + SS] = ((__nv_bfloat16*)&plo)[1];
                    }
                }
            }
        }
    }
}

__global__ __launch_bounds__(128, 3) void qkv_gemm_kernel(
    const float* __restrict__ bq, const float* __restrict__ bk,
    const float* __restrict__ bv)
{
    extern __shared__ char sm[];
    const int z = blockIdx.z;
    if (z == 0)
        gemm_core(g_q_hi, g_q_lo, g_wq_hi, g_wq_lo, bq, nullptr, g_qph, g_qpl, 0, sm);
    else if (z == 1)
        gemm_core(g_k_hi, g_k_lo, g_wk_hi, g_wk_lo, bk, nullptr, g_kph, g_kpl, 0, sm);
    else
        gemm_core(g_v_hi, g_v_lo, g_wv_hi, g_wv_lo, bv, nullptr, g_vth, g_vtl, 2, sm);
}

__global__ __launch_bounds__(128, 3) void outproj_gemm_kernel(
    const float* __restrict__ bo, float* __restrict__ out)
{
    extern __shared__ char sm[];
    gemm_core(g_cx_hi, g_cx_lo, g_wo_hi, g_wo_lo, bo, out, nullptr, nullptr, 1, sm);
}

// ================= tensor-core fused attention (16-query tiles) =================
//   CTA = (bh, 16-query tile). 256 threads (8 warps), 2 CTAs/SM.
//   phase1: logits = Q K^T (128-key chunks, warp key-split), fp32 smem
//   phase2: exact softmax + score gmem write
//   phase3: ctx = P V via split-bf16 mma, warp key-split, smem reduce
#define ATT_KST 72      // bf16 row stride for q / k tiles (144 B)
#define ATT_VST 136     // bf16 row stride for V^T tile (272 B)
#define ATT_SCS 1028    // fp32 logits row stride

#define AOFF_QH 0                         // 16*144 = 2304
#define AOFF_QL 2304
#define AOFF_KB 4608                      // K hi 128*144 = 18432
#define AOFF_KL (AOFF_KB + 18432)         // ends 41472
#define AOFF_VH AOFF_KB                   // V^T hi 64*272 = 17408 (overlay)
#define AOFF_VL (AOFF_KB + 17408)         // ends 39424
#define AOFF_RED AOFF_KB                  // reduce 8*16*64*4 = 32768 (overlay)
#define AOFF_SC 41472                     // fp32 logits 16*1028*4 = 65792
#define ATT_SMEM (AOFF_SC + 16 * ATT_SCS * 4)   // 107264

__global__ __launch_bounds__(256, 2) void attn_kernel(float* __restrict__ score_out)
{
    extern __shared__ char sm[];
    const uint32_t smb = smem_u32(sm);
    float* sc = (float*)(sm + AOFF_SC);

    const int bh  = blockIdx.y;
    const int q0  = blockIdx.x * 16;
    const int tid = threadIdx.x;
    const int lane = tid & 31;
    const int w    = tid >> 5;

    const __nv_bfloat16* qph = g_qph + (size_t)bh * SS * DH;
    const __nv_bfloat16* qpl = g_qpl + (size_t)bh * SS * DH;
    const __nv_bfloat16* kph = g_kph + (size_t)bh * SS * DH;
    const __nv_bfloat16* kpl = g_kpl + (size_t)bh * SS * DH;
    const __nv_bfloat16* vth = g_vth + (size_t)bh * DH * SS;
    const __nv_bfloat16* vtl = g_vtl + (size_t)bh * DH * SS;

    // ---- load q tile (16 x 64) hi/lo ----
    if (tid < 128) {
        int row = tid >> 3, grp = tid & 7;
        size_t src = (size_t)(q0 + row) * DH + grp * 8;
        uint32_t dst = (uint32_t)(row * ATT_KST * 2 + grp * 16);
        *(uint4*)(sm + AOFF_QH + dst) = *(const uint4*)(qph + src);
        *(uint4*)(sm + AOFF_QL + dst) = *(const uint4*)(qpl + src);
    }
    __syncthreads();

    const uint32_t a_off = ((lane & 15) * ATT_KST + (lane >> 4) * 8) * 2;
    const uint32_t b_off = (((lane & 7)) * ATT_KST + ((lane >> 3) & 1) * 8) * 2;
    const uint32_t bv_off = (((lane & 7)) * ATT_VST + ((lane >> 3) & 1) * 8) * 2;

    // ---- phase 1: logits ----
    for (int c0 = 0; c0 < SS; c0 += 128) {
        #pragma unroll
        for (int i = 0; i < 4; i++) {
            int lin = tid + i * 256;
            int row = lin >> 3, grp = lin & 7;
            size_t src = (size_t)(c0 + row) * DH + grp * 8;
            uint32_t dst = (uint32_t)(row * ATT_KST * 2 + grp * 16);
            *(uint4*)(sm + AOFF_KB + dst) = *(const uint4*)(kph + src);
            *(uint4*)(sm + AOFF_KL + dst) = *(const uint4*)(kpl + src);
        }
        __syncthreads();

        float acc[2][4] = {};
        #pragma unroll
        for (int kk = 0; kk < 4; kk++) {
            const uint32_t kby = kk * 32;
            uint32_t ah[4], al[4];
            uint32_t ra = smb + a_off + kby;
            LDSM_X4(ah, ra + AOFF_QH);
            LDSM_X4(al, ra + AOFF_QL);
            #pragma unroll
            for (int nf = 0; nf < 2; nf++) {
                uint32_t rb = smb + b_off
                            + (uint32_t)((w * 16 + nf * 8) * ATT_KST * 2) + kby;
                uint32_t bh[2], bl[2];
                LDSM_X2(bh, rb + AOFF_KB);
                LDSM_X2(bl, rb + AOFF_KL);
                MMA16816(acc[nf], ah, bh);
                MMA16816(acc[nf], ah, bl);
                MMA16816(acc[nf], al, bh);
            }
        }
        #pragma unroll
        for (int nf = 0; nf < 2; nf++) {
            int row = lane >> 2;
            int key = c0 + w * 16 + nf * 8 + (lane & 3) * 2;
            *(float2*)&sc[row * ATT_SCS + key] =
                make_float2(acc[nf][0] * 0.125f, acc[nf][1] * 0.125f);
            *(float2*)&sc[(row + 8) * ATT_SCS + key] =
                make_float2(acc[nf][2] * 0.125f, acc[nf][3] * 0.125f);
        }
        __syncthreads();
    }

    // ---- phase 2: exact softmax + score write ----
    {
        for (int rr = 0; rr < 2; rr++) {
            int r = w * 2 + rr;
            float* row = sc + r * ATT_SCS;
            float mx = row[lane];
            #pragma unroll
            for (int i = 1; i < 32; i++) mx = fmaxf(mx, row[i * 32 + lane]);
            #pragma unroll
            for (int o = 16; o; o >>= 1) mx = fmaxf(mx, __shfl_xor_sync(0xFFFFFFFFu, mx, o));

            float sum = 0.f;
            #pragma unroll
            for (int i = 0; i < 32; i++) {
                float e = __expf(row[i * 32 + lane] - mx);
                row[i * 32 + lane] = e;
                sum += e;
            }
            #pragma unroll
            for (int o = 16; o; o >>= 1) sum += __shfl_xor_sync(0xFFFFFFFFu, sum, o);
            float inv = 1.f / sum;

            float* g = score_out + ((size_t)bh * SS + q0 + r) * SS;
            #pragma unroll
            for (int i = 0; i < 32; i++) {
                float p = row[i * 32 + lane] * inv;
                row[i * 32 + lane] = p;
                __stcs(&g[i * 32 + lane], p);
            }
        }
    }
    __syncthreads();

    // ---- phase 3: ctx = P @ V ----
    {
        float acc[8][4] = {};
        for (int c0 = 0; c0 < SS; c0 += 128) {
            // load V^T chunk (64 e-rows x 128 keys) hi/lo
            #pragma unroll
            for (int i = 0; i < 4; i++) {
                int lin = tid + i * 256;
                int e = lin >> 4, g = lin & 15;
                size_t src = (size_t)e * SS + c0 + g * 8;
                uint32_t dst = (uint32_t)(e * ATT_VST * 2 + g * 16);
                *(uint4*)(sm + AOFF_VH + dst) = *(const uint4*)(vth + src);
                *(uint4*)(sm + AOFF_VL + dst) = *(const uint4*)(vtl + src);
            }
            __syncthreads();

            const int kb = c0 + w * 16;      // this warp's 16 keys
            uint32_t pa_h[4], pa_l[4];
            {
                int r0 = lane >> 2;
                int cc = kb + (lane & 3) * 2;
                float2 p00 = *(float2*)&sc[r0 * ATT_SCS + cc];
                float2 p10 = *(float2*)&sc[(r0 + 8) * ATT_SCS + cc];
                float2 p01 = *(float2*)&sc[r0 * ATT_SCS + cc + 8];
                float2 p11 = *(float2*)&sc[(r0 + 8) * ATT_SCS + cc + 8];
                split_bf2(p00.x, p00.y, pa_h[0], pa_l[0]);
                split_bf2(p10.x, p10.y, pa_h[1], pa_l[1]);
                split_bf2(p01.x, p01.y, pa_h[2], pa_l[2]);
                split_bf2(p11.x, p11.y, pa_h[3], pa_l[3]);
            }
            const uint32_t kwby = (uint32_t)(w * 16 * 2);
            #pragma unroll
            for (int nf = 0; nf < 8; nf++) {
                uint32_t rb = smb + bv_off
                            + (uint32_t)(nf * 8 * ATT_VST * 2) + kwby;
                uint32_t bh[2], bl[2];
                LDSM_X2(bh, rb + AOFF_VH);
                LDSM_X2(bl, rb + AOFF_VL);
                MMA16816(acc[nf], pa_h, bh);
                MMA16816(acc[nf], pa_h, bl);
                MMA16816(acc[nf], pa_l, bh);
            }
            __syncthreads();
        }

        // cross-warp reduce (8 partials of ctx[16][64])
        float* red = (float*)(sm + AOFF_RED);
        #pragma unroll
        for (int nf = 0; nf < 8; nf++) {
            int row = lane >> 2;
            int col = nf * 8 + (lane & 3) * 2;
            *(float2*)&red[w * 1024 + row * 64 + col] =
                make_float2(acc[nf][0], acc[nf][1]);
            *(float2*)&red[w * 1024 + (row + 8) * 64 + col] =
                make_float2(acc[nf][2], acc[nf][3]);
        }
        __syncthreads();

        {
            const int row = tid >> 4;            // 0..15
            const int cg  = (tid & 15) * 4;      // 0..60
            float o[4];
            #pragma unroll
            for (int j = 0; j < 4; j++) {
                float s = 0.f;
                #pragma unroll
                for (int ww = 0; ww < 8; ww++)
                    s += red[ww * 1024 + row * 64 + cg + j];
                o[j] = s;
            }
            const int b = bh >> 4;
            const int h = bh & 15;
            size_t off = ((size_t)b * SS + q0 + row) * DD + h * DH + cg;
            __align__(8) __nv_bfloat16 hb[4], lb[4];
            #pragma unroll
            for (int j = 0; j < 4; j++) {
                hb[j] = __float2bfloat16(o[j]);
                lb[j] = __float2bfloat16(o[j] - __bfloat162float(hb[j]));
            }
            *(uint2*)(g_cx_hi + off) = *(uint2*)hb;
            *(uint2*)(g_cx_lo + off) = *(uint2*)lb;
        }
    }
}

// ============================================================
extern "C" void kernel_launch(void* const* d_in, const int* in_sizes, int n_in,
                              void* d_out, int out_size)
{
    const float* q  = (const float*)d_in[0];
    const float* k  = (const float*)d_in[1];
    const float* v  = (const float*)d_in[2];
    const float* Wq = (const float*)d_in[3];
    const float* bq = (const float*)d_in[4];
    const float* Wk = (const float*)d_in[5];
    const float* bk = (const float*)d_in[6];
    const float* Wv = (const float*)d_in[7];
    const float* bv = (const float*)d_in[8];
    const float* Wo = (const float*)d_in[9];
    const float* bo = (const float*)d_in[10];

    float* out   = (float*)d_out;
    float* score = out + (size_t)BB * SS * DD;

    cudaFuncSetAttribute(attn_kernel,
                         cudaFuncAttributeMaxDynamicSharedMemorySize, ATT_SMEM);
    cudaFuncSetAttribute(qkv_gemm_kernel,
                         cudaFuncAttributeMaxDynamicSharedMemorySize, GEMM_SMEM);
    cudaFuncSetAttribute(outproj_gemm_kernel,
                         cudaFuncAttributeMaxDynamicSharedMemorySize, GEMM_SMEM);

    __nv_bfloat16 *qhi, *qlo, *khi, *klo, *vhi, *vlo;
    __nv_bfloat16 *wqh, *wql, *wkh, *wkl, *wvh, *wvl, *woh, *wol;
    cudaGetSymbolAddress((void**)&qhi, g_q_hi);  cudaGetSymbolAddress((void**)&qlo, g_q_lo);
    cudaGetSymbolAddress((void**)&khi, g_k_hi);  cudaGetSymbolAddress((void**)&klo, g_k_lo);
    cudaGetSymbolAddress((void**)&vhi, g_v_hi);  cudaGetSymbolAddress((void**)&vlo, g_v_lo);
    cudaGetSymbolAddress((void**)&wqh, g_wq_hi); cudaGetSymbolAddress((void**)&wql, g_wq_lo);
    cudaGetSymbolAddress((void**)&wkh, g_wk_hi); cudaGetSymbolAddress((void**)&wkl, g_wk_lo);
    cudaGetSymbolAddress((void**)&wvh, g_wv_hi); cudaGetSymbolAddress((void**)&wvl, g_wv_lo);
    cudaGetSymbolAddress((void**)&woh, g_wo_hi); cudaGetSymbolAddress((void**)&wol, g_wo_lo);

    // 1) convert activations + weights to bf16 hi/lo
    cvt_split_kernel<<<MTOT * DD / 1024, 256>>>(q, qhi, qlo);
    cvt_split_kernel<<<MTOT * DD / 1024, 256>>>(k, khi, klo);
    cvt_split_kernel<<<MTOT * DD / 1024, 256>>>(v, vhi, vlo);
    {
        dim3 g(32, 32), b(32, 8);
        cvt_wt_kernel<<<g, b>>>(Wq, wqh, wql, 1);
        cvt_wt_kernel<<<g, b>>>(Wk, wkh, wkl, 1);
        cvt_wt_kernel<<<g, b>>>(Wv, wvh, wvl, 1);
        cvt_wt_kernel<<<g, b>>>(Wo, woh, wol, 0);
    }

    // 2) fused QKV projections -> bf16 heads (V transposed)
    {
        dim3 g(MTOT / 128, DD / 64, 3);
        qkv_gemm_kernel<<<g, 128, GEMM_SMEM>>>(bq, bk, bv);
    }

    // 3) tensor-core fused attention
    {
        dim3 g(SS / 16, BB * HH);
        attn_kernel<<<g, 256, ATT_SMEM>>>(score);
    }

    // 4) output projection (fp32 out)
    {
        dim3 g(MTOT / 128, DD / 64);
        outproj_gemm_kernel<<<g, 128, GEMM_SMEM>>>(bo, out);
    }
}

// round 7
// speedup vs baseline: 2.9784x; 1.1224x over previous
#include <cuda_runtime.h>
#include <cuda_bf16.h>
#include <cstdint>

#define BB 4
#define SS 1024
#define DD 1024
#define HH 16
#define DH 64
#define MTOT (BB * SS)          // 4096

// ================= scratch (static device memory; no allocs) =================
__device__ __nv_bfloat16 g_q_hi[MTOT * DD], g_q_lo[MTOT * DD];
__device__ __nv_bfloat16 g_k_hi[MTOT * DD], g_k_lo[MTOT * DD];
__device__ __nv_bfloat16 g_v_hi[MTOT * DD], g_v_lo[MTOT * DD];
__device__ __nv_bfloat16 g_wq_hi[DD * DD], g_wq_lo[DD * DD];   // W^T [n][k]
__device__ __nv_bfloat16 g_wk_hi[DD * DD], g_wk_lo[DD * DD];
__device__ __nv_bfloat16 g_wv_hi[DD * DD], g_wv_lo[DD * DD];
__device__ __nv_bfloat16 g_wo_hi[DD * DD], g_wo_lo[DD * DD];
// projected heads
__device__ __nv_bfloat16 g_qph[BB * HH * SS * DH], g_qpl[BB * HH * SS * DH]; // [B,H,S,dh]
__device__ __nv_bfloat16 g_kph[BB * HH * SS * DH], g_kpl[BB * HH * SS * DH];
__device__ __nv_bfloat16 g_vth[BB * HH * DH * SS], g_vtl[BB * HH * DH * SS]; // [B,H,dh,S]
__device__ __nv_bfloat16 g_cx_hi[MTOT * DD], g_cx_lo[MTOT * DD];             // ctx [m][1024]

// ================= helpers =================
static __device__ __forceinline__ uint32_t smem_u32(const void* p) {
    uint32_t a;
    asm("{ .reg .u64 t; cvta.to.shared.u64 t, %1; cvt.u32.u64 %0, t; }"
        : "=r"(a) : "l"(p));
    return a;
}

#define CP_ASYNC16(dst, src) \
    asm volatile("cp.async.cg.shared.global [%0], [%1], 16;" \
                 :: "r"(dst), "l"(src) : "memory")
#define CP_COMMIT()  asm volatile("cp.async.commit_group;" ::: "memory")
#define CP_WAIT(n)   asm volatile("cp.async.wait_group %0;" :: "n"(n) : "memory")

#define LDSM_X4(r, a) \
    asm volatile("ldmatrix.sync.aligned.m8n8.x4.shared.b16 {%0,%1,%2,%3}, [%4];" \
                 : "=r"((r)[0]), "=r"((r)[1]), "=r"((r)[2]), "=r"((r)[3]) : "r"(a))
#define LDSM_X2(r, a) \
    asm volatile("ldmatrix.sync.aligned.m8n8.x2.shared.b16 {%0,%1}, [%2];" \
                 : "=r"((r)[0]), "=r"((r)[1]) : "r"(a))
#define MMA16816(c, a, b) \
    asm volatile("mma.sync.aligned.m16n8k16.row.col.f32.bf16.bf16.f32 " \
                 "{%0,%1,%2,%3}, {%4,%5,%6,%7}, {%8,%9}, {%0,%1,%2,%3};" \
                 : "+f"((c)[0]), "+f"((c)[1]), "+f"((c)[2]), "+f"((c)[3]) \
                 : "r"((a)[0]), "r"((a)[1]), "r"((a)[2]), "r"((a)[3]), \
                   "r"((b)[0]), "r"((b)[1]))

static __device__ __forceinline__ uint32_t pack_bf2(float x, float y) {
    __nv_bfloat16 a = __float2bfloat16(x), b = __float2bfloat16(y);
    uint16_t ua = *(uint16_t*)&a, ub = *(uint16_t*)&b;
    return (uint32_t)ua | ((uint32_t)ub << 16);
}
static __device__ __forceinline__ void split_bf2(float x, float y,
                                                 uint32_t& hi, uint32_t& lo) {
    __nv_bfloat16 hx = __float2bfloat16(x), hy = __float2bfloat16(y);
    float rx = x - __bfloat162float(hx);
    float ry = y - __bfloat162float(hy);
    uint16_t ux = *(uint16_t*)&hx, uy = *(uint16_t*)&hy;
    hi = (uint32_t)ux | ((uint32_t)uy << 16);
    lo = pack_bf2(rx, ry);
}

// ================= conversion kernels =================
__global__ __launch_bounds__(256) void cvt_split_kernel(
    const float* __restrict__ src, __nv_bfloat16* __restrict__ hi,
    __nv_bfloat16* __restrict__ lo)
{
    int i = (blockIdx.x * 256 + threadIdx.x) * 4;
    float4 f = *(const float4*)(src + i);
    __nv_bfloat16 h[4], l[4];
    float v[4] = {f.x, f.y, f.z, f.w};
    #pragma unroll
    for (int j = 0; j < 4; j++) {
        h[j] = __float2bfloat16(v[j]);
        l[j] = __float2bfloat16(v[j] - __bfloat162float(h[j]));
    }
    *(uint2*)(hi + i) = *(uint2*)h;
    *(uint2*)(lo + i) = *(uint2*)l;
}

__global__ __launch_bounds__(256) void cvt_wt_kernel(
    const float* __restrict__ W, __nv_bfloat16* __restrict__ hi,
    __nv_bfloat16* __restrict__ lo, int interleaved)
{
    __shared__ float t[32][33];
    const int tx = threadIdx.x, ty = threadIdx.y;
    const int k0 = blockIdx.x * 32, n0 = blockIdx.y * 32;

    #pragma unroll
    for (int i = 0; i < 4; i++) {
        int k = k0 + ty + i * 8;
        int n = n0 + tx;
        size_t a = interleaved ? ((size_t)(n >> 6) * 65536 + (size_t)k * 64 + (n & 63))
                               : ((size_t)k * 1024 + n);
        t[ty + i * 8][tx] = W[a];
    }
    __syncthreads();
    #pragma unroll
    for (int i = 0; i < 4; i++) {
        int n = n0 + ty + i * 8;
        int k = k0 + tx;
        float v = t[tx][ty + i * 8];
        __nv_bfloat16 h = __float2bfloat16(v);
        hi[(size_t)n * 1024 + k] = h;
        lo[(size_t)n * 1024 + k] = __float2bfloat16(v - __bfloat162float(h));
    }
}

// ================= mma.sync bf16-split GEMM core (unchanged from R6) =========
#define GK 40
#define G_AH 0
#define G_AL 10240
#define G_BH 20480
#define G_BL 25600
#define G_STAGE 30720
#define GEMM_SMEM (2 * G_STAGE)          // 61440

static __device__ __forceinline__ void gemm_core(
    const __nv_bfloat16* __restrict__ Ahi, const __nv_bfloat16* __restrict__ Alo,
    const __nv_bfloat16* __restrict__ Bhi, const __nv_bfloat16* __restrict__ Blo,
    const float* __restrict__ bias, float* __restrict__ Cf,
    __nv_bfloat16* __restrict__ Ch, __nv_bfloat16* __restrict__ Cl, int mode,
    char* sm)
{
    const uint32_t smb = smem_u32(sm);
    const int tid    = threadIdx.x;
    const int lane   = tid & 31;
    const int warp   = tid >> 5;
    const int warp_m = warp >> 1;
    const int warp_n = warp & 1;
    const int m0 = blockIdx.x * 128;
    const int n0 = blockIdx.y * 64;

    const uint32_t aoff = ((warp_m * 64 + (lane & 15)) * GK + ((lane >> 4) * 8)) * 2;
    const uint32_t boff = ((warp_n * 32 + (lane & 7)) * GK + (((lane >> 3) & 1) * 8)) * 2;

    float acc[4][4][4] = {};

    auto issue = [&](int c) {
        const uint32_t sb = smb + (c & 1) * G_STAGE;
        const int k0 = c * 32;
        #pragma unroll
        for (int j = 0; j < 4; j++) {
            int lin = tid + j * 128;
            int row = lin >> 2;
            int cg  = lin & 3;
            uint32_t so = (uint32_t)(row * 80 + cg * 16);
            size_t ga = (size_t)(m0 + row) * DD + k0 + cg * 8;
            CP_ASYNC16(sb + G_AH + so, Ahi + ga);
            CP_ASYNC16(sb + G_AL + so, Alo + ga);
        }
        #pragma unroll
        for (int j = 0; j < 2; j++) {
            int lin = tid + j * 128;
            int row = lin >> 2;
            int cg  = lin & 3;
            uint32_t so = (uint32_t)(row * 80 + cg * 16);
            size_t gb = (size_t)(n0 + row) * DD + k0 + cg * 8;
            CP_ASYNC16(sb + G_BH + so, Bhi + gb);
            CP_ASYNC16(sb + G_BL + so, Blo + gb);
        }
    };

    issue(0);
    CP_COMMIT();

    for (int c = 0; c < DD / 32; c++) {
        if (c + 1 < DD / 32) {
            issue(c + 1);
            CP_COMMIT();
            CP_WAIT(1);
        } else {
            CP_WAIT(0);
        }
        __syncthreads();

        const uint32_t sb = smb + (c & 1) * G_STAGE;
        #pragma unroll
        for (int kk = 0; kk < 2; kk++) {
            const uint32_t kby = kk * 32;
            uint32_t ah[4][4], al[4][4];
            #pragma unroll
            for (int mf = 0; mf < 4; mf++) {
                uint32_t ra = sb + aoff + (uint32_t)(mf * 16 * 80) + kby;
                LDSM_X4(ah[mf], ra + G_AH);
                LDSM_X4(al[mf], ra + G_AL);
            }
            uint32_t bh[4][2], bl[4][2];
            #pragma unroll
            for (int nf = 0; nf < 4; nf++) {
                uint32_t rb = sb + boff + (uint32_t)(nf * 8 * 80) + kby;
                LDSM_X2(bh[nf], rb + G_BH);
                LDSM_X2(bl[nf], rb + G_BL);
            }
            #pragma unroll
            for (int mf = 0; mf < 4; mf++)
                #pragma unroll
                for (int nf = 0; nf < 4; nf++) {
                    MMA16816(acc[mf][nf], ah[mf], bh[nf]);
                    MMA16816(acc[mf][nf], ah[mf], bl[nf]);
                    MMA16816(acc[mf][nf], al[mf], bh[nf]);
                }
        }
        __syncthreads();
    }

    const int lr = lane >> 2;
    const int lc = (lane & 3) * 2;
    #pragma unroll
    for (int mf = 0; mf < 4; mf++) {
        #pragma unroll
        for (int nf = 0; nf < 4; nf++) {
            int n = n0 + warp_n * 32 + nf * 8 + lc;
            float bv0 = bias[n], bv1 = bias[n + 1];
            #pragma unroll
            for (int half = 0; half < 2; half++) {
                int m = m0 + warp_m * 64 + mf * 16 + lr + half * 8;
                float x = acc[mf][nf][half * 2 + 0] + bv0;
                float y = acc[mf][nf][half * 2 + 1] + bv1;
                if (mode == 1) {
                    *(float2*)(Cf + (size_t)m * DD + n) = make_float2(x, y);
                } else {
                    uint32_t phi, plo;
                    split_bf2(x, y, phi, plo);
                    int bidx = m >> 10, s = m & 1023;
                    int h = n >> 6, e = n & 63;
                    if (mode == 0) {
                        size_t off = (((size_t)bidx * HH + h) * SS + s) * DH + e;
                        *(uint32_t*)(Ch + off) = phi;
                        *(uint32_t*)(Cl + off) = plo;
                    } else {
                        size_t off = (((size_t)bidx * HH + h) * DH + e) * SS + s;
                        Ch[off]      = *(__nv_bfloat16*)&phi;
                        Ch[off + SS] = ((__nv_bfloat16*)&phi)[1];
                        Cl[off]      = *(__nv_bfloat16*)&plo;
                        Cl[off + SS] = ((__nv_bfloat16*)&plo)[1];
                    }
                }
            }
        }
    }
}

__global__ __launch_bounds__(128, 3) void qkv_gemm_kernel(
    const float* __restrict__ bq, const float* __restrict__ bk,
    const float* __restrict__ bv)
{
    extern __shared__ char sm[];
    const int z = blockIdx.z;
    if (z == 0)
        gemm_core(g_q_hi, g_q_lo, g_wq_hi, g_wq_lo, bq, nullptr, g_qph, g_qpl, 0, sm);
    else if (z == 1)
        gemm_core(g_k_hi, g_k_lo, g_wk_hi, g_wk_lo, bk, nullptr, g_kph, g_kpl, 0, sm);
    else
        gemm_core(g_v_hi, g_v_lo, g_wv_hi, g_wv_lo, bv, nullptr, g_vth, g_vtl, 2, sm);
}

__global__ __launch_bounds__(128, 3) void outproj_gemm_kernel(
    const float* __restrict__ bo, float* __restrict__ out)
{
    extern __shared__ char sm[];
    gemm_core(g_cx_hi, g_cx_lo, g_wo_hi, g_wo_lo, bo, out, nullptr, nullptr, 1, sm);
}

// ================= tensor-core fused attention (q=32, cp.async 2-stage) ======
//   CTA = (bh, 32-query tile). 256 threads (8 warps), 1 CTA/SM.
//   phase1: logits = Q K^T, 128-key chunks double-buffered via cp.async
//   phase2: exact softmax + score gmem write
//   phase3: ctx = P V, 128-key chunks double-buffered via cp.async
#define ATT_KST 72      // bf16 row stride for q/k (144 B)
#define ATT_VST 136     // bf16 row stride for V^T (272 B)
#define ATT_SCS 1028    // fp32 logits row stride

#define AQ_H 0                            // q hi: 32*144 = 4608
#define AQ_L 4608                         // q lo
#define AK_BASE 9216                      // two K stages of 36864 each
#define AK_STAGE 36864                    // KH 18432 + KL 18432
#define AK_L 18432                        // lo offset within stage
#define AV_L 17408                        // V lo offset within stage (VH 64*272)
#define ARED AK_BASE                      // reduce overlay: 8*32*64*4 = 65536
#define ASC 82944                         // fp32 logits 32*1028*4 = 131584
#define ATT_SMEM (ASC + 32 * ATT_SCS * 4) // 214528

__global__ __launch_bounds__(256, 1) void attn_kernel(float* __restrict__ score_out)
{
    extern __shared__ char sm[];
    const uint32_t smb = smem_u32(sm);
    float* sc = (float*)(sm + ASC);

    const int bh  = blockIdx.y;
    const int q0  = blockIdx.x * 32;
    const int tid = threadIdx.x;
    const int lane = tid & 31;
    const int w    = tid >> 5;

    const __nv_bfloat16* qph = g_qph + (size_t)bh * SS * DH;
    const __nv_bfloat16* qpl = g_qpl + (size_t)bh * SS * DH;
    const __nv_bfloat16* kph = g_kph + (size_t)bh * SS * DH;
    const __nv_bfloat16* kpl = g_kpl + (size_t)bh * SS * DH;
    const __nv_bfloat16* vth = g_vth + (size_t)bh * DH * SS;
    const __nv_bfloat16* vtl = g_vtl + (size_t)bh * DH * SS;

    // ---- load q tile (32 x 64) hi/lo ----
    {
        int row = tid >> 3, grp = tid & 7;
        size_t src = (size_t)(q0 + row) * DH + grp * 8;
        uint32_t dst = (uint32_t)(row * 144 + grp * 16);
        *(uint4*)(sm + AQ_H + dst) = *(const uint4*)(qph + src);
        *(uint4*)(sm + AQ_L + dst) = *(const uint4*)(qpl + src);
    }

    const uint32_t a_off = ((lane & 15) * ATT_KST + (lane >> 4) * 8) * 2;
    const uint32_t b_off = (((lane & 7)) * ATT_KST + ((lane >> 3) & 1) * 8) * 2;
    const uint32_t bv_off = (((lane & 7)) * ATT_VST + ((lane >> 3) & 1) * 8) * 2;

    // ---- phase 1: logits (cp.async double-buffered K chunks) ----
    {
        auto issueK = [&](int c) {
            const uint32_t sb = smb + AK_BASE + (c & 1) * AK_STAGE;
            const int c0 = c * 128;
            #pragma unroll
            for (int i = 0; i < 4; i++) {
                int lin = tid + i * 256;
                int row = lin >> 3, grp = lin & 7;
                size_t src = (size_t)(c0 + row) * DH + grp * 8;
                uint32_t dst = sb + (uint32_t)(row * 144 + grp * 16);
                CP_ASYNC16(dst, kph + src);
                CP_ASYNC16(dst + AK_L, kpl + src);
            }
        };
        issueK(0);
        CP_COMMIT();

        for (int c = 0; c < 8; c++) {
            if (c < 7) { issueK(c + 1); CP_COMMIT(); CP_WAIT(1); }
            else       { CP_WAIT(0); }
            __syncthreads();

            const uint32_t sb = smb + AK_BASE + (c & 1) * AK_STAGE;
            float acc[2][2][4] = {};
            #pragma unroll
            for (int kk = 0; kk < 4; kk++) {
                const uint32_t kby = kk * 32;
                uint32_t ah[2][4], al[2][4];
                #pragma unroll
                for (int mf = 0; mf < 2; mf++) {
                    uint32_t ra = smb + a_off + (uint32_t)(mf * 16 * 144) + kby;
                    LDSM_X4(ah[mf], ra + AQ_H);
                    LDSM_X4(al[mf], ra + AQ_L);
                }
                #pragma unroll
                for (int nf = 0; nf < 2; nf++) {
                    uint32_t rb = sb + b_off
                                + (uint32_t)((w * 16 + nf * 8) * 144) + kby;
                    uint32_t bh[2], bl[2];
                    LDSM_X2(bh, rb);
                    LDSM_X2(bl, rb + AK_L);
                    #pragma unroll
                    for (int mf = 0; mf < 2; mf++) {
                        MMA16816(acc[mf][nf], ah[mf], bh);
                        MMA16816(acc[mf][nf], ah[mf], bl);
                        MMA16816(acc[mf][nf], al[mf], bh);
                    }
                }
            }
            #pragma unroll
            for (int mf = 0; mf < 2; mf++)
                #pragma unroll
                for (int nf = 0; nf < 2; nf++) {
                    int row = mf * 16 + (lane >> 2);
                    int key = c * 128 + w * 16 + nf * 8 + (lane & 3) * 2;
                    *(float2*)&sc[row * ATT_SCS + key] =
                        make_float2(acc[mf][nf][0] * 0.125f, acc[mf][nf][1] * 0.125f);
                    *(float2*)&sc[(row + 8) * ATT_SCS + key] =
                        make_float2(acc[mf][nf][2] * 0.125f, acc[mf][nf][3] * 0.125f);
                }
            __syncthreads();
        }
    }

    // ---- phase 2: exact softmax + score write ----
    {
        for (int rr = 0; rr < 4; rr++) {
            int r = w * 4 + rr;
            float* row = sc + r * ATT_SCS;
            float mx = row[lane];
            #pragma unroll
            for (int i = 1; i < 32; i++) mx = fmaxf(mx, row[i * 32 + lane]);
            #pragma unroll
            for (int o = 16; o; o >>= 1) mx = fmaxf(mx, __shfl_xor_sync(0xFFFFFFFFu, mx, o));

            float sum = 0.f;
            #pragma unroll
            for (int i = 0; i < 32; i++) {
                float e = __expf(row[i * 32 + lane] - mx);
                row[i * 32 + lane] = e;
                sum += e;
            }
            #pragma unroll
            for (int o = 16; o; o >>= 1) sum += __shfl_xor_sync(0xFFFFFFFFu, sum, o);
            float inv = 1.f / sum;

            float* g = score_out + ((size_t)bh * SS + q0 + r) * SS;
            #pragma unroll
            for (int i = 0; i < 32; i++) {
                float p = row[i * 32 + lane] * inv;
                row[i * 32 + lane] = p;
                __stcs(&g[i * 32 + lane], p);
            }
        }
    }
    __syncthreads();

    // ---- phase 3: ctx = P @ V (cp.async double-buffered V chunks) ----
    {
        auto issueV = [&](int c) {
            const uint32_t sb = smb + AK_BASE + (c & 1) * AK_STAGE;
            const int c0 = c * 128;
            #pragma unroll
            for (int i = 0; i < 4; i++) {
                int lin = tid + i * 256;
                int e = lin >> 4, g = lin & 15;
                size_t src = (size_t)e * SS + c0 + g * 8;
                uint32_t dst = sb + (uint32_t)(e * 272 + g * 16);
                CP_ASYNC16(dst, vth + src);
                CP_ASYNC16(dst + AV_L, vtl + src);
            }
        };
        issueV(0);
        CP_COMMIT();

        float acc[2][8][4] = {};
        for (int c = 0; c < 8; c++) {
            if (c < 7) { issueV(c + 1); CP_COMMIT(); CP_WAIT(1); }
            else       { CP_WAIT(0); }
            __syncthreads();

            const uint32_t sb = smb + AK_BASE + (c & 1) * AK_STAGE;
            const int kb = c * 128 + w * 16;   // this warp's 16 keys
            uint32_t pa_h[2][4], pa_l[2][4];
            #pragma unroll
            for (int mf = 0; mf < 2; mf++) {
                int r0 = mf * 16 + (lane >> 2);
                int cc = kb + (lane & 3) * 2;
                float2 p00 = *(float2*)&sc[r0 * ATT_SCS + cc];
                float2 p10 = *(float2*)&sc[(r0 + 8) * ATT_SCS + cc];
                float2 p01 = *(float2*)&sc[r0 * ATT_SCS + cc + 8];
                float2 p11 = *(float2*)&sc[(r0 + 8) * ATT_SCS + cc + 8];
                split_bf2(p00.x, p00.y, pa_h[mf][0], pa_l[mf][0]);
                split_bf2(p10.x, p10.y, pa_h[mf][1], pa_l[mf][1]);
                split_bf2(p01.x, p01.y, pa_h[mf][2], pa_l[mf][2]);
                split_bf2(p11.x, p11.y, pa_h[mf][3], pa_l[mf][3]);
            }
            const uint32_t kwby = (uint32_t)(w * 16 * 2);
            #pragma unroll
            for (int nf = 0; nf < 8; nf++) {
                uint32_t rb = sb + bv_off + (uint32_t)(nf * 8 * 272) + kwby;
                uint32_t bh[2], bl[2];
                LDSM_X2(bh, rb);
                LDSM_X2(bl, rb + AV_L);
                #pragma unroll
                for (int mf = 0; mf < 2; mf++) {
                    MMA16816(acc[mf][nf], pa_h[mf], bh);
                    MMA16816(acc[mf][nf], pa_h[mf], bl);
                    MMA16816(acc[mf][nf], pa_l[mf], bh);
                }
            }
            __syncthreads();
        }

        // cross-warp reduce (8 partials of ctx[32][64])
        float* red = (float*)(sm + ARED);
        #pragma unroll
        for (int mf = 0; mf < 2; mf++)
            #pragma unroll
            for (int nf = 0; nf < 8; nf++) {
                int row = mf * 16 + (lane >> 2);
                int col = nf * 8 + (lane & 3) * 2;
                *(float2*)&red[w * 2048 + row * 64 + col] =
                    make_float2(acc[mf][nf][0], acc[mf][nf][1]);
                *(float2*)&red[w * 2048 + (row + 8) * 64 + col] =
                    make_float2(acc[mf][nf][2], acc[mf][nf][3]);
            }
        __syncthreads();

        {
            const int row = tid >> 3;            // 0..31
            const int cg  = (tid & 7) * 8;       // 0..56
            float o[8];
            #pragma unroll
            for (int j = 0; j < 8; j++) {
                float s = 0.f;
                #pragma unroll
                for (int ww = 0; ww < 8; ww++)
                    s += red[ww * 2048 + row * 64 + cg + j];
                o[j] = s;
            }
            const int b = bh >> 4;
            const int h = bh & 15;
            size_t off = ((size_t)b * SS + q0 + row) * DD + h * DH + cg;
            __align__(16) __nv_bfloat16 hb[8], lb[8];
            #pragma unroll
            for (int j = 0; j < 8; j++) {
                hb[j] = __float2bfloat16(o[j]);
                lb[j] = __float2bfloat16(o[j] - __bfloat162float(hb[j]));
            }
            *(uint4*)(g_cx_hi + off) = *(uint4*)hb;
            *(uint4*)(g_cx_lo + off) = *(uint4*)lb;
        }
    }
}

// ============================================================
extern "C" void kernel_launch(void* const* d_in, const int* in_sizes, int n_in,
                              void* d_out, int out_size)
{
    const float* q  = (const float*)d_in[0];
    const float* k  = (const float*)d_in[1];
    const float* v  = (const float*)d_in[2];
    const float* Wq = (const float*)d_in[3];
    const float* bq = (const float*)d_in[4];
    const float* Wk = (const float*)d_in[5];
    const float* bk = (const float*)d_in[6];
    const float* Wv = (const float*)d_in[7];
    const float* bv = (const float*)d_in[8];
    const float* Wo = (const float*)d_in[9];
    const float* bo = (const float*)d_in[10];

    float* out   = (float*)d_out;
    float* score = out + (size_t)BB * SS * DD;

    cudaFuncSetAttribute(attn_kernel,
                         cudaFuncAttributeMaxDynamicSharedMemorySize, ATT_SMEM);
    cudaFuncSetAttribute(qkv_gemm_kernel,
                         cudaFuncAttributeMaxDynamicSharedMemorySize, GEMM_SMEM);
    cudaFuncSetAttribute(outproj_gemm_kernel,
                         cudaFuncAttributeMaxDynamicSharedMemorySize, GEMM_SMEM);

    __nv_bfloat16 *qhi, *qlo, *khi, *klo, *vhi, *vlo;
    __nv_bfloat16 *wqh, *wql, *wkh, *wkl, *wvh, *wvl, *woh, *wol;
    cudaGetSymbolAddress((void**)&qhi, g_q_hi);  cudaGetSymbolAddress((void**)&qlo, g_q_lo);
    cudaGetSymbolAddress((void**)&khi, g_k_hi);  cudaGetSymbolAddress((void**)&klo, g_k_lo);
    cudaGetSymbolAddress((void**)&vhi, g_v_hi);  cudaGetSymbolAddress((void**)&vlo, g_v_lo);
    cudaGetSymbolAddress((void**)&wqh, g_wq_hi); cudaGetSymbolAddress((void**)&wql, g_wq_lo);
    cudaGetSymbolAddress((void**)&wkh, g_wk_hi); cudaGetSymbolAddress((void**)&wkl, g_wk_lo);
    cudaGetSymbolAddress((void**)&wvh, g_wv_hi); cudaGetSymbolAddress((void**)&wvl, g_wv_lo);
    cudaGetSymbolAddress((void**)&woh, g_wo_hi); cudaGetSymbolAddress((void**)&wol, g_wo_lo);

    // 1) convert activations + weights to bf16 hi/lo
    cvt_split_kernel<<<MTOT * DD / 1024, 256>>>(q, qhi, qlo);
    cvt_split_kernel<<<MTOT * DD / 1024, 256>>>(k, khi, klo);
    cvt_split_kernel<<<MTOT * DD / 1024, 256>>>(v, vhi, vlo);
    {
        dim3 g(32, 32), b(32, 8);
        cvt_wt_kernel<<<g, b>>>(Wq, wqh, wql, 1);
        cvt_wt_kernel<<<g, b>>>(Wk, wkh, wkl, 1);
        cvt_wt_kernel<<<g, b>>>(Wv, wvh, wvl, 1);
        cvt_wt_kernel<<<g, b>>>(Wo, woh, wol, 0);
    }

    // 2) fused QKV projections -> bf16 heads (V transposed)
    {
        dim3 g(MTOT / 128, DD / 64, 3);
        qkv_gemm_kernel<<<g, 128, GEMM_SMEM>>>(bq, bk, bv);
    }

    // 3) tensor-core fused attention
    {
        dim3 g(SS / 32, BB * HH);
        attn_kernel<<<g, 256, ATT_SMEM>>>(score);
    }

    // 4) output projection (fp32 out)
    {
        dim3 g(MTOT / 128, DD / 64);
        outproj_gemm_kernel<<<g, 128, GEMM_SMEM>>>(bo, out);
    }
}